// round 14
// baseline (speedup 1.0000x reference)
#include <cuda_runtime.h>
#include <cuda_fp16.h>
#include <math.h>
#include <stdint.h>

#define BS   2
#define SEQ  2048
#define DIM  1024
#define HID  4096
#define NH   16
#define DPH  64
#define MROWS (BS*SEQ)   // 4096

// ---------------- scratch (no allocation allowed) ----------------
__device__ __half g_q  [MROWS*DIM];
__device__ __half g_k  [MROWS*DIM];
__device__ __half g_v  [MROWS*DIM];
__device__ __half g_ctx[MROWS*DIM];
__device__ __half g_h1t[MROWS*DIM];
__device__ __half g_ffn[MROWS*HID];
__device__ __half g_xt [MROWS*DIM];
__device__ __half g_wqh[DIM*DIM];
__device__ __half g_wkh[DIM*DIM];
__device__ __half g_wvh[DIM*DIM];
__device__ __half g_woh[DIM*DIM];
__device__ __half g_w1h[DIM*HID];
__device__ __half g_w2h[HID*DIM];
__device__ __half g_saH[MROWS*DIM];
__device__ __half g_f2H[MROWS*DIM];
__device__ float  g_h1 [MROWS*DIM];

__device__ __forceinline__ uint32_t smem_u32(const void* p) {
    uint32_t a;
    asm("{ .reg .u64 t; cvta.to.shared.u64 t, %1; cvt.u32.u64 %0, t; }" : "=r"(a) : "l"(p));
    return a;
}
__device__ __forceinline__ void cp_async16(uint32_t dst, const void* src) {
    asm volatile("cp.async.cg.shared.global [%0], [%1], 16;" :: "r"(dst), "l"(src));
}
#define CP_COMMIT() asm volatile("cp.async.commit_group;" ::: "memory")
#define CP_WAIT(n)  asm volatile("cp.async.wait_group %0;" :: "n"(n) : "memory")

__device__ __forceinline__ void ldmatrix_x4(uint32_t& r0, uint32_t& r1, uint32_t& r2, uint32_t& r3,
                                            uint32_t addr) {
    asm volatile("ldmatrix.sync.aligned.m8n8.x4.shared.b16 {%0,%1,%2,%3}, [%4];"
        : "=r"(r0), "=r"(r1), "=r"(r2), "=r"(r3) : "r"(addr));
}
__device__ __forceinline__ void ldmatrix_x4_trans(uint32_t& r0, uint32_t& r1, uint32_t& r2, uint32_t& r3,
                                                  uint32_t addr) {
    asm volatile("ldmatrix.sync.aligned.m8n8.x4.trans.shared.b16 {%0,%1,%2,%3}, [%4];"
        : "=r"(r0), "=r"(r1), "=r"(r2), "=r"(r3) : "r"(addr));
}

__device__ __forceinline__ void mma_f16(float* d,
                                        uint32_t a0, uint32_t a1, uint32_t a2, uint32_t a3,
                                        uint32_t b0, uint32_t b1) {
    asm volatile(
        "mma.sync.aligned.m16n8k16.row.col.f32.f16.f16.f32 "
        "{%0,%1,%2,%3}, {%4,%5,%6,%7}, {%8,%9}, {%0,%1,%2,%3};"
        : "+f"(d[0]), "+f"(d[1]), "+f"(d[2]), "+f"(d[3])
        : "r"(a0), "r"(a1), "r"(a2), "r"(a3), "r"(b0), "r"(b1));
}

__device__ __forceinline__ uint32_t pack_h2(float a, float b) {
    __half2 h = __floats2half2_rn(a, b);
    return *(uint32_t*)&h;
}

__device__ __forceinline__ float gelu_f(float x) {
    return 0.5f * x * (1.0f + erff(x * 0.70710678118654752f));
}

// ---------------- merged prep: fp32 -> fp16 for x + all 6 weights ----------------
#define C_X  (MROWS*DIM/4)
#define C_W  (DIM*DIM/4)
#define C_F  (DIM*HID/4)
#define CB1  (C_X)
#define CB2  (CB1 + C_W)
#define CB3  (CB2 + C_W)
#define CB4  (CB3 + C_W)
#define CB5  (CB4 + C_W)
#define CB6  (CB5 + C_F)
#define CB7  (CB6 + C_F)

__global__ void cvt_all_kernel(const float* __restrict__ x,
                               const float* __restrict__ wq, const float* __restrict__ wk,
                               const float* __restrict__ wv, const float* __restrict__ wo,
                               const float* __restrict__ w1, const float* __restrict__ w2,
                               __half* __restrict__ xt,
                               __half* __restrict__ wqh, __half* __restrict__ wkh,
                               __half* __restrict__ wvh, __half* __restrict__ woh,
                               __half* __restrict__ w1h, __half* __restrict__ w2h) {
    for (int i = blockIdx.x * blockDim.x + threadIdx.x; i < CB7; i += gridDim.x * blockDim.x) {
        const float* in;
        __half* out;
        int off;
        if      (i < CB1) { in = x;  out = xt;  off = i; }
        else if (i < CB2) { in = wq; out = wqh; off = i - CB1; }
        else if (i < CB3) { in = wk; out = wkh; off = i - CB2; }
        else if (i < CB4) { in = wv; out = wvh; off = i - CB3; }
        else if (i < CB5) { in = wo; out = woh; off = i - CB4; }
        else if (i < CB6) { in = w1; out = w1h; off = i - CB5; }
        else              { in = w2; out = w2h; off = i - CB6; }
        float4 v = ((const float4*)in)[off];
        uint2 u;
        u.x = pack_h2(v.x, v.y);
        u.y = pack_h2(v.z, v.w);
        ((uint2*)out)[off] = u;
    }
}

// ---------------- fp16 GEMM: 128x128 CTA tile, 4 warps, warp tile 64x64 ----------------
#define AS 72
#define BT 136
#define A_TILE_BYTES (128 * AS * 2)
#define B_TILE_BYTES (64 * BT * 2)
#define G_STAGE_BYTES (A_TILE_BYTES + B_TILE_BYTES)
#define GEMM_SMEM_BYTES (3 * G_STAGE_BYTES)

template<int ACT, int HOUT>
__device__ __forceinline__ void gemm_body(const __half* __restrict__ A,
                                          const __half* __restrict__ W,
                                          const float* __restrict__ bias,
                                          void* __restrict__ Cv,
                                          int K, int N, int m0, int n0, float oscale) {
    extern __shared__ uint32_t dsm[];
    const uint32_t sb = smem_u32(dsm);

    const int tid  = threadIdx.x;
    const int lane = tid & 31;
    const int wid  = tid >> 5;              // 0..3
    const int grp  = lane >> 2;
    const int t4   = lane & 3;
    const int ts   = lane >> 3;
    const int r8   = lane & 7;
    const int wm = (wid & 1) * 64;          // warp M offset
    const int wn = (wid >> 1) * 64;         // warp N offset

    const uint32_t a_loff = (uint32_t)((((ts & 1) * 8 + r8) * AS) * 2 + (ts >> 1) * 16);
    const uint32_t b_loff = (uint32_t)((((ts & 1) * 8 + r8) * BT) * 2 + (ts >> 1) * 16);

    float acc[4][8][4];
    #pragma unroll
    for (int i = 0; i < 4; i++)
        #pragma unroll
        for (int j = 0; j < 8; j++)
            #pragma unroll
            for (int c = 0; c < 4; c++) acc[i][j][c] = 0.0f;

    const int nit = K / 64;

    auto load_stage = [&](int s, int it) {
        const uint32_t base = sb + (uint32_t)s * G_STAGE_BYTES;
        #pragma unroll
        for (int j = 0; j < 8; j++) {
            int idx = tid + j * 128;
            int row = idx >> 3, c = idx & 7;
            cp_async16(base + (uint32_t)(row * AS * 2 + c * 16),
                       A + (size_t)(m0 + row) * K + it * 64 + c * 8);
        }
        #pragma unroll
        for (int j = 0; j < 8; j++) {
            int idx = tid + j * 128;
            int k = idx >> 4, nb = (idx & 15) * 8;
            cp_async16(base + (uint32_t)A_TILE_BYTES + (uint32_t)(k * BT * 2 + nb * 2),
                       W + (size_t)(it * 64 + k) * N + n0 + nb);
        }
    };

    load_stage(0, 0);
    CP_COMMIT();
    if (nit > 1) { load_stage(1, 1); }
    CP_COMMIT();

    for (int it = 0; it < nit; it++) {
        const int s = it % 3;
        CP_WAIT(1);
        __syncthreads();
        if (it + 2 < nit) load_stage((it + 2) % 3, it + 2);
        CP_COMMIT();

        const uint32_t sA = sb + (uint32_t)s * G_STAGE_BYTES + (uint32_t)(wm * AS * 2) + a_loff;
        const uint32_t sB = sb + (uint32_t)s * G_STAGE_BYTES + (uint32_t)A_TILE_BYTES
                          + (uint32_t)(wn * 2) + b_loff;
        #pragma unroll
        for (int kk = 0; kk < 4; kk++) {
            uint32_t afr[4][4];
            #pragma unroll
            for (int mt = 0; mt < 4; mt++)
                ldmatrix_x4(afr[mt][0], afr[mt][1], afr[mt][2], afr[mt][3],
                            sA + (uint32_t)(mt * 16 * AS * 2) + (uint32_t)(kk * 32));
            uint32_t bfr[8][2];
            #pragma unroll
            for (int np = 0; np < 4; np++)
                ldmatrix_x4_trans(bfr[2*np][0], bfr[2*np][1], bfr[2*np+1][0], bfr[2*np+1][1],
                                  sB + (uint32_t)(kk * 16 * BT * 2) + (uint32_t)(np * 32));
            #pragma unroll
            for (int mt = 0; mt < 4; mt++)
                #pragma unroll
                for (int nt = 0; nt < 8; nt++)
                    mma_f16(acc[mt][nt], afr[mt][0], afr[mt][1], afr[mt][2], afr[mt][3],
                            bfr[nt][0], bfr[nt][1]);
        }
    }

    #pragma unroll
    for (int mt = 0; mt < 4; mt++) {
        #pragma unroll
        for (int nt = 0; nt < 8; nt++) {
            const int col = n0 + wn + nt * 8 + t4 * 2;
            const float b0v = bias[col], b1v = bias[col + 1];
            const int r0 = m0 + wm + mt * 16 + grp;
            float v0 = (acc[mt][nt][0] + b0v) * oscale;
            float v1 = (acc[mt][nt][1] + b1v) * oscale;
            float v2 = (acc[mt][nt][2] + b0v) * oscale;
            float v3 = (acc[mt][nt][3] + b1v) * oscale;
            if (ACT == 1) { v0 = gelu_f(v0); v1 = gelu_f(v1); v2 = gelu_f(v2); v3 = gelu_f(v3); }
            if (HOUT) {
                __half* Ch = (__half*)Cv;
                *(uint32_t*)&Ch[(size_t)r0 * N + col]       = pack_h2(v0, v1);
                *(uint32_t*)&Ch[(size_t)(r0 + 8) * N + col] = pack_h2(v2, v3);
            } else {
                float* Cf = (float*)Cv;
                *(float2*)&Cf[(size_t)r0 * N + col]       = make_float2(v0, v1);
                *(float2*)&Cf[(size_t)(r0 + 8) * N + col] = make_float2(v2, v3);
            }
        }
    }
}

template<int ACT, int HOUT>
__global__ void __launch_bounds__(128, 2)
gemm_cp(const __half* __restrict__ A, const __half* __restrict__ W,
        const float* __restrict__ bias, void* __restrict__ C, int K, int N) {
    gemm_body<ACT, HOUT>(A, W, bias, C, K, N, blockIdx.y * 128, blockIdx.x * 128, 1.0f);
}

__global__ void __launch_bounds__(128, 2)
qkv_gemm(const __half* __restrict__ xt,
         const __half* __restrict__ wq, const __half* __restrict__ wk, const __half* __restrict__ wv,
         const float* __restrict__ bq, const float* __restrict__ bk, const float* __restrict__ bv,
         __half* __restrict__ q, __half* __restrict__ k, __half* __restrict__ v) {
    const int sel = blockIdx.x >> 3;
    const __half* W   = (sel == 0) ? wq : (sel == 1) ? wk : wv;
    const float* bias = (sel == 0) ? bq : (sel == 1) ? bk : bv;
    __half*      C    = (sel == 0) ? q  : (sel == 1) ? k  : v;
    const float scale = (sel == 0) ? 0.125f : 1.0f;
    gemm_body<0, 1>(xt, W, bias, C, DIM, DIM, blockIdx.y * 128, (blockIdx.x & 7) * 128, scale);
}

// ---------------- fp16 flash attention: 3-stage K/V pipeline (unchanged) ----------------
#define HS 72
#define AT_QB  (128 * HS * 2)
#define AT_TB  (64 * HS * 2)
#define AT_STAGE (2 * AT_TB)
#define ATTN_SMEM_BYTES (AT_QB + 3 * AT_STAGE + 768)

__global__ void __launch_bounds__(256, 2)
attn_mma(const __half* __restrict__ Q, const __half* __restrict__ K,
         const __half* __restrict__ V, const int* __restrict__ mask,
         __half* __restrict__ ctx) {
    extern __shared__ uint32_t asm_[];
    const uint32_t sb = smem_u32(asm_);
    float* smaskb = (float*)((char*)asm_ + AT_QB + 3 * AT_STAGE);

    const int tid  = threadIdx.x;
    const int lane = tid & 31;
    const int wid  = tid >> 5;
    const int grp  = lane >> 2;
    const int t4   = lane & 3;
    const int ts   = lane >> 3;
    const int r8   = lane & 7;
    const int w16  = wid * 16;
    const int q0 = blockIdx.x * 128;
    const int h  = blockIdx.y;
    const int b  = blockIdx.z;
    const size_t base = (size_t)b * SEQ * DIM + h * DPH;

    const uint32_t q_loff = (uint32_t)(((w16 + (ts & 1) * 8 + r8) * HS) * 2 + (ts >> 1) * 16);
    const uint32_t k_loff = (uint32_t)((((ts >> 1) * 8 + r8) * HS) * 2 + (ts & 1) * 16);
    const uint32_t v_loff = (uint32_t)((((ts & 1) * 8 + r8) * HS) * 2 + (ts >> 1) * 16);

    float o[8][4];
    #pragma unroll
    for (int nf = 0; nf < 8; nf++)
        #pragma unroll
        for (int c = 0; c < 4; c++) o[nf][c] = 0.0f;
    float mrow0 = -INFINITY, mrow1 = -INFINITY;
    float l0 = 0.0f, l1 = 0.0f;

    auto load_kv = [&](int s, int it) {
        const uint32_t kb = sb + (uint32_t)AT_QB + (uint32_t)s * AT_STAGE;
        const int kv0 = it * 64;
        #pragma unroll
        for (int j = 0; j < 2; j++) {
            int idx = tid + j * 256;
            int row = idx >> 3, c = idx & 7;
            size_t g = base + (size_t)(kv0 + row) * DIM + c * 8;
            cp_async16(kb + (uint32_t)(row * HS * 2 + c * 16), K + g);
            cp_async16(kb + (uint32_t)AT_TB + (uint32_t)(row * HS * 2 + c * 16), V + g);
        }
        if (tid < 64)
            smaskb[s * 64 + tid] = (mask[b * SEQ + kv0 + tid] == 0) ? -INFINITY : 0.0f;
    };

    {
        #pragma unroll
        for (int j = 0; j < 4; j++) {
            int idx = tid + j * 256;
            int row = idx >> 3, c = idx & 7;
            cp_async16(sb + (uint32_t)(row * HS * 2 + c * 16),
                       Q + base + (size_t)(q0 + row) * DIM + c * 8);
        }
        load_kv(0, 0);
        CP_COMMIT();
        load_kv(1, 1);
        CP_COMMIT();
    }

    const int nt_tiles = SEQ / 64;
    for (int it = 0; it < nt_tiles; it++) {
        const int s = it % 3;
        CP_WAIT(1);
        __syncthreads();
        if (it + 2 < nt_tiles) load_kv((it + 2) % 3, it + 2);
        CP_COMMIT();

        const uint32_t sbK = sb + (uint32_t)AT_QB + (uint32_t)s * AT_STAGE + k_loff;
        const uint32_t sbV = sb + (uint32_t)AT_QB + (uint32_t)s * AT_STAGE + (uint32_t)AT_TB + v_loff;
        const float* smask = smaskb + s * 64;

        float sacc[8][4];
        #pragma unroll
        for (int nf = 0; nf < 8; nf++)
            #pragma unroll
            for (int c = 0; c < 4; c++) sacc[nf][c] = 0.0f;
        #pragma unroll
        for (int kk = 0; kk < 4; kk++) {
            const uint32_t kb = kk * 32;
            uint32_t qa0, qa1, qa2, qa3;
            ldmatrix_x4(qa0, qa1, qa2, qa3, sb + q_loff + kb);
            #pragma unroll
            for (int np = 0; np < 4; np++) {
                uint32_t b00, b01, b10, b11;
                ldmatrix_x4(b00, b01, b10, b11,
                            sbK + (uint32_t)(np * 16 * HS * 2) + kb);
                mma_f16(sacc[2*np],   qa0, qa1, qa2, qa3, b00, b01);
                mma_f16(sacc[2*np+1], qa0, qa1, qa2, qa3, b10, b11);
            }
        }

        #pragma unroll
        for (int nf = 0; nf < 8; nf++) {
            float mv0 = smask[nf * 8 + t4 * 2];
            float mv1 = smask[nf * 8 + t4 * 2 + 1];
            sacc[nf][0] += mv0; sacc[nf][1] += mv1;
            sacc[nf][2] += mv0; sacc[nf][3] += mv1;
        }

        float mt0 = -INFINITY, mt1 = -INFINITY;
        #pragma unroll
        for (int nf = 0; nf < 8; nf++) {
            mt0 = fmaxf(mt0, fmaxf(sacc[nf][0], sacc[nf][1]));
            mt1 = fmaxf(mt1, fmaxf(sacc[nf][2], sacc[nf][3]));
        }
        mt0 = fmaxf(mt0, __shfl_xor_sync(0xffffffffu, mt0, 1));
        mt0 = fmaxf(mt0, __shfl_xor_sync(0xffffffffu, mt0, 2));
        mt1 = fmaxf(mt1, __shfl_xor_sync(0xffffffffu, mt1, 1));
        mt1 = fmaxf(mt1, __shfl_xor_sync(0xffffffffu, mt1, 2));
        float mnew0 = fmaxf(mrow0, mt0);
        float mnew1 = fmaxf(mrow1, mt1);
        float alpha0 = __expf(mrow0 - mnew0);
        float alpha1 = __expf(mrow1 - mnew1);
        float lsum0 = 0.0f, lsum1 = 0.0f;
        #pragma unroll
        for (int nf = 0; nf < 8; nf++) {
            sacc[nf][0] = __expf(sacc[nf][0] - mnew0);
            sacc[nf][1] = __expf(sacc[nf][1] - mnew0);
            sacc[nf][2] = __expf(sacc[nf][2] - mnew1);
            sacc[nf][3] = __expf(sacc[nf][3] - mnew1);
            lsum0 += sacc[nf][0] + sacc[nf][1];
            lsum1 += sacc[nf][2] + sacc[nf][3];
        }
        lsum0 += __shfl_xor_sync(0xffffffffu, lsum0, 1);
        lsum0 += __shfl_xor_sync(0xffffffffu, lsum0, 2);
        lsum1 += __shfl_xor_sync(0xffffffffu, lsum1, 1);
        lsum1 += __shfl_xor_sync(0xffffffffu, lsum1, 2);
        l0 = l0 * alpha0 + lsum0;
        l1 = l1 * alpha1 + lsum1;
        mrow0 = mnew0; mrow1 = mnew1;
        #pragma unroll
        for (int nf = 0; nf < 8; nf++) {
            o[nf][0] *= alpha0; o[nf][1] *= alpha0;
            o[nf][2] *= alpha1; o[nf][3] *= alpha1;
        }

        #pragma unroll
        for (int c = 0; c < 4; c++) {
            uint32_t a0 = pack_h2(sacc[2*c][0],   sacc[2*c][1]);
            uint32_t a1 = pack_h2(sacc[2*c][2],   sacc[2*c][3]);
            uint32_t a2 = pack_h2(sacc[2*c+1][0], sacc[2*c+1][1]);
            uint32_t a3 = pack_h2(sacc[2*c+1][2], sacc[2*c+1][3]);
            const uint32_t rowoff = (uint32_t)(c * 16 * HS * 2);
            #pragma unroll
            for (int np = 0; np < 4; np++) {
                uint32_t b00, b01, b10, b11;
                ldmatrix_x4_trans(b00, b01, b10, b11,
                                  sbV + rowoff + (uint32_t)(np * 32));
                mma_f16(o[2*np],   a0, a1, a2, a3, b00, b01);
                mma_f16(o[2*np+1], a0, a1, a2, a3, b10, b11);
            }
        }
    }

    const float inv0 = 1.0f / l0;
    const float inv1 = 1.0f / l1;
    const int r0 = q0 + w16 + grp;
    #pragma unroll
    for (int nf = 0; nf < 8; nf++) {
        const int d0 = nf * 8 + t4 * 2;
        *(uint32_t*)&ctx[base + (size_t)r0 * DIM + d0] =
            pack_h2(o[nf][0] * inv0, o[nf][1] * inv0);
        *(uint32_t*)&ctx[base + (size_t)(r0 + 8) * DIM + d0] =
            pack_h2(o[nf][2] * inv1, o[nf][3] * inv1);
    }
}

// ---------------- residual + LayerNorm: a fp16, residual fp32 ----------------
template<int HOUT>
__global__ void ln_residual_kernel(const __half* __restrict__ a,
                                   const float* __restrict__ r,
                                   const float* __restrict__ gamma,
                                   const float* __restrict__ beta,
                                   float* __restrict__ out,
                                   __half* __restrict__ out_t) {
    const int row = blockIdx.x;
    const int tid = threadIdx.x;

    uint2 ua = ((const uint2*)(a + (size_t)row * DIM))[tid];
    __half2 a01 = *(__half2*)&ua.x;
    __half2 a23 = *(__half2*)&ua.y;
    float4 vr = ((const float4*)(r + (size_t)row * DIM))[tid];
    float v[4] = { __low2float(a01) + vr.x, __high2float(a01) + vr.y,
                   __low2float(a23) + vr.z, __high2float(a23) + vr.w };
    float sum = v[0] + v[1] + v[2] + v[3];
    float sq  = v[0]*v[0] + v[1]*v[1] + v[2]*v[2] + v[3]*v[3];

    #pragma unroll
    for (int off = 16; off >= 1; off >>= 1) {
        sum += __shfl_xor_sync(0xffffffffu, sum, off);
        sq  += __shfl_xor_sync(0xffffffffu, sq,  off);
    }
    __shared__ float ssum[8], ssq[8];
    int warp = tid >> 5, lane = tid & 31;
    if (lane == 0) { ssum[warp] = sum; ssq[warp] = sq; }
    __syncthreads();
    sum = 0.0f; sq = 0.0f;
    #pragma unroll
    for (int i = 0; i < 8; i++) { sum += ssum[i]; sq += ssq[i]; }

    const float invN = 1.0f / (float)DIM;
    float mu  = sum * invN;
    float var = fmaxf(sq * invN - mu * mu, 0.0f);
    float rstd = rsqrtf(var + 1e-12f);

    float4 g4 = ((const float4*)gamma)[tid];
    float4 b4 = ((const float4*)beta)[tid];
    float4 o4;
    o4.x = (v[0] - mu) * rstd * g4.x + b4.x;
    o4.y = (v[1] - mu) * rstd * g4.y + b4.y;
    o4.z = (v[2] - mu) * rstd * g4.z + b4.z;
    o4.w = (v[3] - mu) * rstd * g4.w + b4.w;
    ((float4*)(out + (size_t)row * DIM))[tid] = o4;
    if (HOUT) {
        uint2 u;
        u.x = pack_h2(o4.x, o4.y);
        u.y = pack_h2(o4.z, o4.w);
        ((uint2*)(out_t + (size_t)row * DIM))[tid] = u;
    }
}

// ---------------- launch ----------------
extern "C" void kernel_launch(void* const* d_in, const int* in_sizes, int n_in,
                              void* d_out, int out_size) {
    const float* x    = (const float*)d_in[0];
    const int*   mask = (const int*)  d_in[1];
    const float* Wq   = (const float*)d_in[2];
    const float* bq   = (const float*)d_in[3];
    const float* Wk   = (const float*)d_in[4];
    const float* bk   = (const float*)d_in[5];
    const float* Wv   = (const float*)d_in[6];
    const float* bv   = (const float*)d_in[7];
    const float* Wo   = (const float*)d_in[8];
    const float* bo   = (const float*)d_in[9];
    const float* ln1g = (const float*)d_in[10];
    const float* ln1b = (const float*)d_in[11];
    const float* W1   = (const float*)d_in[12];
    const float* b1   = (const float*)d_in[13];
    const float* W2   = (const float*)d_in[14];
    const float* b2   = (const float*)d_in[15];
    const float* ln2g = (const float*)d_in[16];
    const float* ln2b = (const float*)d_in[17];
    float* out = (float*)d_out;

    __half *q, *k, *v, *ctx, *h1t, *ffn, *xt, *wqh, *wkh, *wvh, *woh, *w1h, *w2h, *saH, *f2H;
    float *h1;
    cudaGetSymbolAddress((void**)&q,   g_q);
    cudaGetSymbolAddress((void**)&k,   g_k);
    cudaGetSymbolAddress((void**)&v,   g_v);
    cudaGetSymbolAddress((void**)&ctx, g_ctx);
    cudaGetSymbolAddress((void**)&h1t, g_h1t);
    cudaGetSymbolAddress((void**)&ffn, g_ffn);
    cudaGetSymbolAddress((void**)&xt,  g_xt);
    cudaGetSymbolAddress((void**)&wqh, g_wqh);
    cudaGetSymbolAddress((void**)&wkh, g_wkh);
    cudaGetSymbolAddress((void**)&wvh, g_wvh);
    cudaGetSymbolAddress((void**)&woh, g_woh);
    cudaGetSymbolAddress((void**)&w1h, g_w1h);
    cudaGetSymbolAddress((void**)&w2h, g_w2h);
    cudaGetSymbolAddress((void**)&saH, g_saH);
    cudaGetSymbolAddress((void**)&f2H, g_f2H);
    cudaGetSymbolAddress((void**)&h1,  g_h1);

    cudaFuncSetAttribute(qkv_gemm,      cudaFuncAttributeMaxDynamicSharedMemorySize, GEMM_SMEM_BYTES);
    cudaFuncSetAttribute(gemm_cp<0,1>,  cudaFuncAttributeMaxDynamicSharedMemorySize, GEMM_SMEM_BYTES);
    cudaFuncSetAttribute(gemm_cp<1,1>,  cudaFuncAttributeMaxDynamicSharedMemorySize, GEMM_SMEM_BYTES);
    cudaFuncSetAttribute(attn_mma,      cudaFuncAttributeMaxDynamicSharedMemorySize, ATTN_SMEM_BYTES);

    // single merged prep pass
    cvt_all_kernel<<<2048, 256>>>(x, Wq, Wk, Wv, Wo, W1, W2,
                                  xt, wqh, wkh, wvh, woh, w1h, w2h);

    // fused QKV (fp16 out; q pre-scaled by 0.125)
    qkv_gemm<<<dim3(24, MROWS/128), 128, GEMM_SMEM_BYTES>>>(xt, wqh, wkh, wvh, bq, bk, bv, q, k, v);

    // attention (fp16 in/out)
    attn_mma<<<dim3(SEQ/128, NH, BS), 256, ATTN_SMEM_BYTES>>>(q, k, v, mask, ctx);

    // Wo projection -> sa fp16
    gemm_cp<0,1><<<dim3(DIM/128, MROWS/128), 128, GEMM_SMEM_BYTES>>>(ctx, woh, bo, saH, DIM, DIM);

    // LN1(sa + x) -> h1 fp32 + h1t fp16
    ln_residual_kernel<1><<<MROWS, 256>>>(saH, x, ln1g, ln1b, h1, h1t);

    // FFN1 (gelu, fp16 out), FFN2 (fp16 out)
    gemm_cp<1,1><<<dim3(HID/128, MROWS/128), 128, GEMM_SMEM_BYTES>>>(h1t, w1h, b1, ffn, DIM, HID);
    gemm_cp<0,1><<<dim3(DIM/128, MROWS/128), 128, GEMM_SMEM_BYTES>>>(ffn, w2h, b2, f2H, HID, DIM);

    // LN2(f2 + h1) -> out
    ln_residual_kernel<0><<<MROWS, 256>>>(f2H, h1, ln2g, ln2b, out, nullptr);
}

// round 15
// speedup vs baseline: 1.0401x; 1.0401x over previous
#include <cuda_runtime.h>
#include <cuda_fp16.h>
#include <math.h>
#include <stdint.h>

#define BS   2
#define SEQ  2048
#define DIM  1024
#define HID  4096
#define NH   16
#define DPH  64
#define MROWS (BS*SEQ)   // 4096

// ---------------- scratch (no allocation allowed) ----------------
__device__ __half g_q  [MROWS*DIM];
__device__ __half g_k  [MROWS*DIM];
__device__ __half g_v  [MROWS*DIM];
__device__ __half g_ctx[MROWS*DIM];
__device__ __half g_h1t[MROWS*DIM];
__device__ __half g_ffn[MROWS*HID];
__device__ __half g_xt [MROWS*DIM];
__device__ __half g_wqh[DIM*DIM];
__device__ __half g_wkh[DIM*DIM];
__device__ __half g_wvh[DIM*DIM];
__device__ __half g_woh[DIM*DIM];
__device__ __half g_w1h[DIM*HID];
__device__ __half g_w2h[HID*DIM];
__device__ __half g_saH[MROWS*DIM];
__device__ __half g_f2H[MROWS*DIM];
__device__ float  g_h1 [MROWS*DIM];

__device__ __forceinline__ uint32_t smem_u32(const void* p) {
    uint32_t a;
    asm("{ .reg .u64 t; cvta.to.shared.u64 t, %1; cvt.u32.u64 %0, t; }" : "=r"(a) : "l"(p));
    return a;
}
__device__ __forceinline__ void cp_async16(uint32_t dst, const void* src) {
    asm volatile("cp.async.cg.shared.global [%0], [%1], 16;" :: "r"(dst), "l"(src));
}
#define CP_COMMIT() asm volatile("cp.async.commit_group;" ::: "memory")
#define CP_WAIT(n)  asm volatile("cp.async.wait_group %0;" :: "n"(n) : "memory")

__device__ __forceinline__ void ldmatrix_x4(uint32_t& r0, uint32_t& r1, uint32_t& r2, uint32_t& r3,
                                            uint32_t addr) {
    asm volatile("ldmatrix.sync.aligned.m8n8.x4.shared.b16 {%0,%1,%2,%3}, [%4];"
        : "=r"(r0), "=r"(r1), "=r"(r2), "=r"(r3) : "r"(addr));
}
__device__ __forceinline__ void ldmatrix_x4_trans(uint32_t& r0, uint32_t& r1, uint32_t& r2, uint32_t& r3,
                                                  uint32_t addr) {
    asm volatile("ldmatrix.sync.aligned.m8n8.x4.trans.shared.b16 {%0,%1,%2,%3}, [%4];"
        : "=r"(r0), "=r"(r1), "=r"(r2), "=r"(r3) : "r"(addr));
}

__device__ __forceinline__ void mma_f16(float* d,
                                        uint32_t a0, uint32_t a1, uint32_t a2, uint32_t a3,
                                        uint32_t b0, uint32_t b1) {
    asm volatile(
        "mma.sync.aligned.m16n8k16.row.col.f32.f16.f16.f32 "
        "{%0,%1,%2,%3}, {%4,%5,%6,%7}, {%8,%9}, {%0,%1,%2,%3};"
        : "+f"(d[0]), "+f"(d[1]), "+f"(d[2]), "+f"(d[3])
        : "r"(a0), "r"(a1), "r"(a2), "r"(a3), "r"(b0), "r"(b1));
}

__device__ __forceinline__ uint32_t pack_h2(float a, float b) {
    __half2 h = __floats2half2_rn(a, b);
    return *(uint32_t*)&h;
}

__device__ __forceinline__ float gelu_f(float x) {
    return 0.5f * x * (1.0f + erff(x * 0.70710678118654752f));
}

// ---------------- merged prep: fp32 -> fp16 for x + all 6 weights ----------------
#define C_X  (MROWS*DIM/4)
#define C_W  (DIM*DIM/4)
#define C_F  (DIM*HID/4)
#define CB1  (C_X)
#define CB2  (CB1 + C_W)
#define CB3  (CB2 + C_W)
#define CB4  (CB3 + C_W)
#define CB5  (CB4 + C_W)
#define CB6  (CB5 + C_F)
#define CB7  (CB6 + C_F)

__global__ void cvt_all_kernel(const float* __restrict__ x,
                               const float* __restrict__ wq, const float* __restrict__ wk,
                               const float* __restrict__ wv, const float* __restrict__ wo,
                               const float* __restrict__ w1, const float* __restrict__ w2,
                               __half* __restrict__ xt,
                               __half* __restrict__ wqh, __half* __restrict__ wkh,
                               __half* __restrict__ wvh, __half* __restrict__ woh,
                               __half* __restrict__ w1h, __half* __restrict__ w2h) {
    for (int i = blockIdx.x * blockDim.x + threadIdx.x; i < CB7; i += gridDim.x * blockDim.x) {
        const float* in;
        __half* out;
        int off;
        if      (i < CB1) { in = x;  out = xt;  off = i; }
        else if (i < CB2) { in = wq; out = wqh; off = i - CB1; }
        else if (i < CB3) { in = wk; out = wkh; off = i - CB2; }
        else if (i < CB4) { in = wv; out = wvh; off = i - CB3; }
        else if (i < CB5) { in = wo; out = woh; off = i - CB4; }
        else if (i < CB6) { in = w1; out = w1h; off = i - CB5; }
        else              { in = w2; out = w2h; off = i - CB6; }
        float4 v = ((const float4*)in)[off];
        uint2 u;
        u.x = pack_h2(v.x, v.y);
        u.y = pack_h2(v.z, v.w);
        ((uint2*)out)[off] = u;
    }
}

// ---------------- fp16 GEMM: 128x128 CTA, 8 warps (R13 champion config) ----------------
#define AS 72
#define BT 136
#define A_TILE_BYTES (128 * AS * 2)
#define B_TILE_BYTES (64 * BT * 2)
#define G_STAGE_BYTES (A_TILE_BYTES + B_TILE_BYTES)
#define GEMM_SMEM_BYTES (3 * G_STAGE_BYTES)

template<int ACT, int HOUT>
__device__ __forceinline__ void gemm_body(const __half* __restrict__ A,
                                          const __half* __restrict__ W,
                                          const float* __restrict__ bias,
                                          void* __restrict__ Cv,
                                          int K, int N, int m0, int n0, float oscale) {
    extern __shared__ uint32_t dsm[];
    const uint32_t sb = smem_u32(dsm);

    const int tid  = threadIdx.x;
    const int lane = tid & 31;
    const int wid  = tid >> 5;
    const int grp  = lane >> 2;
    const int t4   = lane & 3;
    const int ts   = lane >> 3;
    const int r8   = lane & 7;
    const int wm = (wid & 3) * 32;
    const int wn = (wid >> 2) * 64;

    const uint32_t a_loff = (uint32_t)((((ts & 1) * 8 + r8) * AS) * 2 + (ts >> 1) * 16);
    const uint32_t b_loff = (uint32_t)((((ts & 1) * 8 + r8) * BT) * 2 + (ts >> 1) * 16);

    float acc[2][8][4];
    #pragma unroll
    for (int i = 0; i < 2; i++)
        #pragma unroll
        for (int j = 0; j < 8; j++)
            #pragma unroll
            for (int c = 0; c < 4; c++) acc[i][j][c] = 0.0f;

    const int nit = K / 64;

    auto load_stage = [&](int s, int it) {
        const uint32_t base = sb + (uint32_t)s * G_STAGE_BYTES;
        #pragma unroll
        for (int j = 0; j < 4; j++) {
            int idx = tid + j * 256;
            int row = idx >> 3, c = idx & 7;
            cp_async16(base + (uint32_t)(row * AS * 2 + c * 16),
                       A + (size_t)(m0 + row) * K + it * 64 + c * 8);
        }
        #pragma unroll
        for (int j = 0; j < 4; j++) {
            int idx = tid + j * 256;
            int k = idx >> 4, nb = (idx & 15) * 8;
            cp_async16(base + (uint32_t)A_TILE_BYTES + (uint32_t)(k * BT * 2 + nb * 2),
                       W + (size_t)(it * 64 + k) * N + n0 + nb);
        }
    };

    load_stage(0, 0);
    CP_COMMIT();
    if (nit > 1) { load_stage(1, 1); }
    CP_COMMIT();

    for (int it = 0; it < nit; it++) {
        const int s = it % 3;
        CP_WAIT(1);
        __syncthreads();
        if (it + 2 < nit) load_stage((it + 2) % 3, it + 2);
        CP_COMMIT();

        const uint32_t sA = sb + (uint32_t)s * G_STAGE_BYTES + (uint32_t)(wm * AS * 2) + a_loff;
        const uint32_t sB = sb + (uint32_t)s * G_STAGE_BYTES + (uint32_t)A_TILE_BYTES
                          + (uint32_t)(wn * 2) + b_loff;
        #pragma unroll
        for (int kk = 0; kk < 4; kk++) {
            uint32_t afr[2][4];
            #pragma unroll
            for (int mt = 0; mt < 2; mt++)
                ldmatrix_x4(afr[mt][0], afr[mt][1], afr[mt][2], afr[mt][3],
                            sA + (uint32_t)(mt * 16 * AS * 2) + (uint32_t)(kk * 32));
            uint32_t bfr[8][2];
            #pragma unroll
            for (int np = 0; np < 4; np++)
                ldmatrix_x4_trans(bfr[2*np][0], bfr[2*np][1], bfr[2*np+1][0], bfr[2*np+1][1],
                                  sB + (uint32_t)(kk * 16 * BT * 2) + (uint32_t)(np * 32));
            #pragma unroll
            for (int mt = 0; mt < 2; mt++)
                #pragma unroll
                for (int nt = 0; nt < 8; nt++)
                    mma_f16(acc[mt][nt], afr[mt][0], afr[mt][1], afr[mt][2], afr[mt][3],
                            bfr[nt][0], bfr[nt][1]);
        }
    }

    #pragma unroll
    for (int mt = 0; mt < 2; mt++) {
        #pragma unroll
        for (int nt = 0; nt < 8; nt++) {
            const int col = n0 + wn + nt * 8 + t4 * 2;
            const float b0v = bias[col], b1v = bias[col + 1];
            const int r0 = m0 + wm + mt * 16 + grp;
            float v0 = (acc[mt][nt][0] + b0v) * oscale;
            float v1 = (acc[mt][nt][1] + b1v) * oscale;
            float v2 = (acc[mt][nt][2] + b0v) * oscale;
            float v3 = (acc[mt][nt][3] + b1v) * oscale;
            if (ACT == 1) { v0 = gelu_f(v0); v1 = gelu_f(v1); v2 = gelu_f(v2); v3 = gelu_f(v3); }
            if (HOUT) {
                __half* Ch = (__half*)Cv;
                *(uint32_t*)&Ch[(size_t)r0 * N + col]       = pack_h2(v0, v1);
                *(uint32_t*)&Ch[(size_t)(r0 + 8) * N + col] = pack_h2(v2, v3);
            } else {
                float* Cf = (float*)Cv;
                *(float2*)&Cf[(size_t)r0 * N + col]       = make_float2(v0, v1);
                *(float2*)&Cf[(size_t)(r0 + 8) * N + col] = make_float2(v2, v3);
            }
        }
    }
}

template<int ACT, int HOUT>
__global__ void __launch_bounds__(256, 2)
gemm_cp(const __half* __restrict__ A, const __half* __restrict__ W,
        const float* __restrict__ bias, void* __restrict__ C, int K, int N) {
    gemm_body<ACT, HOUT>(A, W, bias, C, K, N, blockIdx.y * 128, blockIdx.x * 128, 1.0f);
}

__global__ void __launch_bounds__(256, 2)
qkv_gemm(const __half* __restrict__ xt,
         const __half* __restrict__ wq, const __half* __restrict__ wk, const __half* __restrict__ wv,
         const float* __restrict__ bq, const float* __restrict__ bk, const float* __restrict__ bv,
         __half* __restrict__ q, __half* __restrict__ k, __half* __restrict__ v) {
    const int sel = blockIdx.x >> 3;
    const __half* W   = (sel == 0) ? wq : (sel == 1) ? wk : wv;
    const float* bias = (sel == 0) ? bq : (sel == 1) ? bk : bv;
    __half*      C    = (sel == 0) ? q  : (sel == 1) ? k  : v;
    const float scale = (sel == 0) ? 0.125f : 1.0f;
    gemm_body<0, 1>(xt, W, bias, C, DIM, DIM, blockIdx.y * 128, (blockIdx.x & 7) * 128, scale);
}

// ---------------- fp16 flash attention: 3-stage K/V pipeline (R13) ----------------
#define HS 72
#define AT_QB  (128 * HS * 2)
#define AT_TB  (64 * HS * 2)
#define AT_STAGE (2 * AT_TB)
#define ATTN_SMEM_BYTES (AT_QB + 3 * AT_STAGE + 768)

__global__ void __launch_bounds__(256, 2)
attn_mma(const __half* __restrict__ Q, const __half* __restrict__ K,
         const __half* __restrict__ V, const int* __restrict__ mask,
         __half* __restrict__ ctx) {
    extern __shared__ uint32_t asm_[];
    const uint32_t sb = smem_u32(asm_);
    float* smaskb = (float*)((char*)asm_ + AT_QB + 3 * AT_STAGE);

    const int tid  = threadIdx.x;
    const int lane = tid & 31;
    const int wid  = tid >> 5;
    const int grp  = lane >> 2;
    const int t4   = lane & 3;
    const int ts   = lane >> 3;
    const int r8   = lane & 7;
    const int w16  = wid * 16;
    const int q0 = blockIdx.x * 128;
    const int h  = blockIdx.y;
    const int b  = blockIdx.z;
    const size_t base = (size_t)b * SEQ * DIM + h * DPH;

    const uint32_t q_loff = (uint32_t)(((w16 + (ts & 1) * 8 + r8) * HS) * 2 + (ts >> 1) * 16);
    const uint32_t k_loff = (uint32_t)((((ts >> 1) * 8 + r8) * HS) * 2 + (ts & 1) * 16);
    const uint32_t v_loff = (uint32_t)((((ts & 1) * 8 + r8) * HS) * 2 + (ts >> 1) * 16);

    float o[8][4];
    #pragma unroll
    for (int nf = 0; nf < 8; nf++)
        #pragma unroll
        for (int c = 0; c < 4; c++) o[nf][c] = 0.0f;
    float mrow0 = -INFINITY, mrow1 = -INFINITY;
    float l0 = 0.0f, l1 = 0.0f;

    auto load_kv = [&](int s, int it) {
        const uint32_t kb = sb + (uint32_t)AT_QB + (uint32_t)s * AT_STAGE;
        const int kv0 = it * 64;
        #pragma unroll
        for (int j = 0; j < 2; j++) {
            int idx = tid + j * 256;
            int row = idx >> 3, c = idx & 7;
            size_t g = base + (size_t)(kv0 + row) * DIM + c * 8;
            cp_async16(kb + (uint32_t)(row * HS * 2 + c * 16), K + g);
            cp_async16(kb + (uint32_t)AT_TB + (uint32_t)(row * HS * 2 + c * 16), V + g);
        }
        if (tid < 64)
            smaskb[s * 64 + tid] = (mask[b * SEQ + kv0 + tid] == 0) ? -INFINITY : 0.0f;
    };

    {
        #pragma unroll
        for (int j = 0; j < 4; j++) {
            int idx = tid + j * 256;
            int row = idx >> 3, c = idx & 7;
            cp_async16(sb + (uint32_t)(row * HS * 2 + c * 16),
                       Q + base + (size_t)(q0 + row) * DIM + c * 8);
        }
        load_kv(0, 0);
        CP_COMMIT();
        load_kv(1, 1);
        CP_COMMIT();
    }

    const int nt_tiles = SEQ / 64;
    for (int it = 0; it < nt_tiles; it++) {
        const int s = it % 3;
        CP_WAIT(1);
        __syncthreads();
        if (it + 2 < nt_tiles) load_kv((it + 2) % 3, it + 2);
        CP_COMMIT();

        const uint32_t sbK = sb + (uint32_t)AT_QB + (uint32_t)s * AT_STAGE + k_loff;
        const uint32_t sbV = sb + (uint32_t)AT_QB + (uint32_t)s * AT_STAGE + (uint32_t)AT_TB + v_loff;
        const float* smask = smaskb + s * 64;

        float sacc[8][4];
        #pragma unroll
        for (int nf = 0; nf < 8; nf++)
            #pragma unroll
            for (int c = 0; c < 4; c++) sacc[nf][c] = 0.0f;
        #pragma unroll
        for (int kk = 0; kk < 4; kk++) {
            const uint32_t kb = kk * 32;
            uint32_t qa0, qa1, qa2, qa3;
            ldmatrix_x4(qa0, qa1, qa2, qa3, sb + q_loff + kb);
            #pragma unroll
            for (int np = 0; np < 4; np++) {
                uint32_t b00, b01, b10, b11;
                ldmatrix_x4(b00, b01, b10, b11,
                            sbK + (uint32_t)(np * 16 * HS * 2) + kb);
                mma_f16(sacc[2*np],   qa0, qa1, qa2, qa3, b00, b01);
                mma_f16(sacc[2*np+1], qa0, qa1, qa2, qa3, b10, b11);
            }
        }

        #pragma unroll
        for (int nf = 0; nf < 8; nf++) {
            float mv0 = smask[nf * 8 + t4 * 2];
            float mv1 = smask[nf * 8 + t4 * 2 + 1];
            sacc[nf][0] += mv0; sacc[nf][1] += mv1;
            sacc[nf][2] += mv0; sacc[nf][3] += mv1;
        }

        float mt0 = -INFINITY, mt1 = -INFINITY;
        #pragma unroll
        for (int nf = 0; nf < 8; nf++) {
            mt0 = fmaxf(mt0, fmaxf(sacc[nf][0], sacc[nf][1]));
            mt1 = fmaxf(mt1, fmaxf(sacc[nf][2], sacc[nf][3]));
        }
        mt0 = fmaxf(mt0, __shfl_xor_sync(0xffffffffu, mt0, 1));
        mt0 = fmaxf(mt0, __shfl_xor_sync(0xffffffffu, mt0, 2));
        mt1 = fmaxf(mt1, __shfl_xor_sync(0xffffffffu, mt1, 1));
        mt1 = fmaxf(mt1, __shfl_xor_sync(0xffffffffu, mt1, 2));
        float mnew0 = fmaxf(mrow0, mt0);
        float mnew1 = fmaxf(mrow1, mt1);
        float alpha0 = __expf(mrow0 - mnew0);
        float alpha1 = __expf(mrow1 - mnew1);
        float lsum0 = 0.0f, lsum1 = 0.0f;
        #pragma unroll
        for (int nf = 0; nf < 8; nf++) {
            sacc[nf][0] = __expf(sacc[nf][0] - mnew0);
            sacc[nf][1] = __expf(sacc[nf][1] - mnew0);
            sacc[nf][2] = __expf(sacc[nf][2] - mnew1);
            sacc[nf][3] = __expf(sacc[nf][3] - mnew1);
            lsum0 += sacc[nf][0] + sacc[nf][1];
            lsum1 += sacc[nf][2] + sacc[nf][3];
        }
        lsum0 += __shfl_xor_sync(0xffffffffu, lsum0, 1);
        lsum0 += __shfl_xor_sync(0xffffffffu, lsum0, 2);
        lsum1 += __shfl_xor_sync(0xffffffffu, lsum1, 1);
        lsum1 += __shfl_xor_sync(0xffffffffu, lsum1, 2);
        l0 = l0 * alpha0 + lsum0;
        l1 = l1 * alpha1 + lsum1;
        mrow0 = mnew0; mrow1 = mnew1;
        #pragma unroll
        for (int nf = 0; nf < 8; nf++) {
            o[nf][0] *= alpha0; o[nf][1] *= alpha0;
            o[nf][2] *= alpha1; o[nf][3] *= alpha1;
        }

        #pragma unroll
        for (int c = 0; c < 4; c++) {
            uint32_t a0 = pack_h2(sacc[2*c][0],   sacc[2*c][1]);
            uint32_t a1 = pack_h2(sacc[2*c][2],   sacc[2*c][3]);
            uint32_t a2 = pack_h2(sacc[2*c+1][0], sacc[2*c+1][1]);
            uint32_t a3 = pack_h2(sacc[2*c+1][2], sacc[2*c+1][3]);
            const uint32_t rowoff = (uint32_t)(c * 16 * HS * 2);
            #pragma unroll
            for (int np = 0; np < 4; np++) {
                uint32_t b00, b01, b10, b11;
                ldmatrix_x4_trans(b00, b01, b10, b11,
                                  sbV + rowoff + (uint32_t)(np * 32));
                mma_f16(o[2*np],   a0, a1, a2, a3, b00, b01);
                mma_f16(o[2*np+1], a0, a1, a2, a3, b10, b11);
            }
        }
    }

    const float inv0 = 1.0f / l0;
    const float inv1 = 1.0f / l1;
    const int r0 = q0 + w16 + grp;
    #pragma unroll
    for (int nf = 0; nf < 8; nf++) {
        const int d0 = nf * 8 + t4 * 2;
        *(uint32_t*)&ctx[base + (size_t)r0 * DIM + d0] =
            pack_h2(o[nf][0] * inv0, o[nf][1] * inv0);
        *(uint32_t*)&ctx[base + (size_t)(r0 + 8) * DIM + d0] =
            pack_h2(o[nf][2] * inv1, o[nf][3] * inv1);
    }
}

// ---------------- residual + LayerNorm: 2 rows per block, 128 threads/row ----------------
template<int HOUT>
__global__ void ln_residual_kernel(const __half* __restrict__ a,
                                   const float* __restrict__ r,
                                   const float* __restrict__ gamma,
                                   const float* __restrict__ beta,
                                   float* __restrict__ out,
                                   __half* __restrict__ out_t) {
    const int tid = threadIdx.x;
    const int sub = tid >> 7;                 // 0 or 1: which row of the pair
    const int t   = tid & 127;                // thread within row
    const int row = blockIdx.x * 2 + sub;

    const __half* pa = a + (size_t)row * DIM;
    const float*  pr = r + (size_t)row * DIM;

    // 8 floats per thread: two uint2 (fp16) + two float4
    uint2 ua0 = ((const uint2*)pa)[t * 2];
    uint2 ua1 = ((const uint2*)pa)[t * 2 + 1];
    float4 vr0 = ((const float4*)pr)[t * 2];
    float4 vr1 = ((const float4*)pr)[t * 2 + 1];
    __half2 a01 = *(__half2*)&ua0.x;
    __half2 a23 = *(__half2*)&ua0.y;
    __half2 a45 = *(__half2*)&ua1.x;
    __half2 a67 = *(__half2*)&ua1.y;
    float v[8] = { __low2float(a01) + vr0.x, __high2float(a01) + vr0.y,
                   __low2float(a23) + vr0.z, __high2float(a23) + vr0.w,
                   __low2float(a45) + vr1.x, __high2float(a45) + vr1.y,
                   __low2float(a67) + vr1.z, __high2float(a67) + vr1.w };
    float sum = 0.0f, sq = 0.0f;
    #pragma unroll
    for (int i = 0; i < 8; i++) { sum += v[i]; sq += v[i] * v[i]; }

    #pragma unroll
    for (int off = 16; off >= 1; off >>= 1) {
        sum += __shfl_xor_sync(0xffffffffu, sum, off);
        sq  += __shfl_xor_sync(0xffffffffu, sq,  off);
    }
    __shared__ float ssum[8], ssq[8];
    int warp = tid >> 5, lane = tid & 31;
    if (lane == 0) { ssum[warp] = sum; ssq[warp] = sq; }
    __syncthreads();
    // combine the 4 warps of this row (warps sub*4 .. sub*4+3)
    sum = 0.0f; sq = 0.0f;
    #pragma unroll
    for (int i = 0; i < 4; i++) { sum += ssum[sub * 4 + i]; sq += ssq[sub * 4 + i]; }

    const float invN = 1.0f / (float)DIM;
    float mu  = sum * invN;
    float var = fmaxf(sq * invN - mu * mu, 0.0f);
    float rstd = rsqrtf(var + 1e-12f);

    float4 g0 = ((const float4*)gamma)[t * 2];
    float4 g1 = ((const float4*)gamma)[t * 2 + 1];
    float4 b0 = ((const float4*)beta)[t * 2];
    float4 b1 = ((const float4*)beta)[t * 2 + 1];
    float4 o0, o1;
    o0.x = (v[0] - mu) * rstd * g0.x + b0.x;
    o0.y = (v[1] - mu) * rstd * g0.y + b0.y;
    o0.z = (v[2] - mu) * rstd * g0.z + b0.z;
    o0.w = (v[3] - mu) * rstd * g0.w + b0.w;
    o1.x = (v[4] - mu) * rstd * g1.x + b1.x;
    o1.y = (v[5] - mu) * rstd * g1.y + b1.y;
    o1.z = (v[6] - mu) * rstd * g1.z + b1.z;
    o1.w = (v[7] - mu) * rstd * g1.w + b1.w;
    ((float4*)(out + (size_t)row * DIM))[t * 2]     = o0;
    ((float4*)(out + (size_t)row * DIM))[t * 2 + 1] = o1;
    if (HOUT) {
        uint2 u0, u1;
        u0.x = pack_h2(o0.x, o0.y); u0.y = pack_h2(o0.z, o0.w);
        u1.x = pack_h2(o1.x, o1.y); u1.y = pack_h2(o1.z, o1.w);
        ((uint2*)(out_t + (size_t)row * DIM))[t * 2]     = u0;
        ((uint2*)(out_t + (size_t)row * DIM))[t * 2 + 1] = u1;
    }
}

// ---------------- launch ----------------
extern "C" void kernel_launch(void* const* d_in, const int* in_sizes, int n_in,
                              void* d_out, int out_size) {
    const float* x    = (const float*)d_in[0];
    const int*   mask = (const int*)  d_in[1];
    const float* Wq   = (const float*)d_in[2];
    const float* bq   = (const float*)d_in[3];
    const float* Wk   = (const float*)d_in[4];
    const float* bk   = (const float*)d_in[5];
    const float* Wv   = (const float*)d_in[6];
    const float* bv   = (const float*)d_in[7];
    const float* Wo   = (const float*)d_in[8];
    const float* bo   = (const float*)d_in[9];
    const float* ln1g = (const float*)d_in[10];
    const float* ln1b = (const float*)d_in[11];
    const float* W1   = (const float*)d_in[12];
    const float* b1   = (const float*)d_in[13];
    const float* W2   = (const float*)d_in[14];
    const float* b2   = (const float*)d_in[15];
    const float* ln2g = (const float*)d_in[16];
    const float* ln2b = (const float*)d_in[17];
    float* out = (float*)d_out;

    __half *q, *k, *v, *ctx, *h1t, *ffn, *xt, *wqh, *wkh, *wvh, *woh, *w1h, *w2h, *saH, *f2H;
    float *h1;
    cudaGetSymbolAddress((void**)&q,   g_q);
    cudaGetSymbolAddress((void**)&k,   g_k);
    cudaGetSymbolAddress((void**)&v,   g_v);
    cudaGetSymbolAddress((void**)&ctx, g_ctx);
    cudaGetSymbolAddress((void**)&h1t, g_h1t);
    cudaGetSymbolAddress((void**)&ffn, g_ffn);
    cudaGetSymbolAddress((void**)&xt,  g_xt);
    cudaGetSymbolAddress((void**)&wqh, g_wqh);
    cudaGetSymbolAddress((void**)&wkh, g_wkh);
    cudaGetSymbolAddress((void**)&wvh, g_wvh);
    cudaGetSymbolAddress((void**)&woh, g_woh);
    cudaGetSymbolAddress((void**)&w1h, g_w1h);
    cudaGetSymbolAddress((void**)&w2h, g_w2h);
    cudaGetSymbolAddress((void**)&saH, g_saH);
    cudaGetSymbolAddress((void**)&f2H, g_f2H);
    cudaGetSymbolAddress((void**)&h1,  g_h1);

    cudaFuncSetAttribute(qkv_gemm,      cudaFuncAttributeMaxDynamicSharedMemorySize, GEMM_SMEM_BYTES);
    cudaFuncSetAttribute(gemm_cp<0,1>,  cudaFuncAttributeMaxDynamicSharedMemorySize, GEMM_SMEM_BYTES);
    cudaFuncSetAttribute(gemm_cp<1,1>,  cudaFuncAttributeMaxDynamicSharedMemorySize, GEMM_SMEM_BYTES);
    cudaFuncSetAttribute(attn_mma,      cudaFuncAttributeMaxDynamicSharedMemorySize, ATTN_SMEM_BYTES);

    // single merged prep pass
    cvt_all_kernel<<<2048, 256>>>(x, Wq, Wk, Wv, Wo, W1, W2,
                                  xt, wqh, wkh, wvh, woh, w1h, w2h);

    // fused QKV (fp16 out; q pre-scaled by 0.125)
    qkv_gemm<<<dim3(24, MROWS/128), 256, GEMM_SMEM_BYTES>>>(xt, wqh, wkh, wvh, bq, bk, bv, q, k, v);

    // attention (fp16 in/out)
    attn_mma<<<dim3(SEQ/128, NH, BS), 256, ATTN_SMEM_BYTES>>>(q, k, v, mask, ctx);

    // Wo projection -> sa fp16
    gemm_cp<0,1><<<dim3(DIM/128, MROWS/128), 256, GEMM_SMEM_BYTES>>>(ctx, woh, bo, saH, DIM, DIM);

    // LN1(sa + x) -> h1 fp32 + h1t fp16
    ln_residual_kernel<1><<<MROWS/2, 256>>>(saH, x, ln1g, ln1b, h1, h1t);

    // FFN1 (gelu, fp16 out), FFN2 (fp16 out)
    gemm_cp<1,1><<<dim3(HID/128, MROWS/128), 256, GEMM_SMEM_BYTES>>>(h1t, w1h, b1, ffn, DIM, HID);
    gemm_cp<0,1><<<dim3(DIM/128, MROWS/128), 256, GEMM_SMEM_BYTES>>>(ffn, w2h, b2, f2H, HID, DIM);

    // LN2(f2 + h1) -> out
    ln_residual_kernel<0><<<MROWS/2, 256>>>(f2H, h1, ln2g, ln2b, out, nullptr);
}

// round 16
// speedup vs baseline: 1.0444x; 1.0041x over previous
#include <cuda_runtime.h>
#include <cuda_fp16.h>
#include <math.h>
#include <stdint.h>

#define BS   2
#define SEQ  2048
#define DIM  1024
#define HID  4096
#define NH   16
#define DPH  64
#define MROWS (BS*SEQ)   // 4096

// ---------------- scratch (no allocation allowed) ----------------
__device__ __half g_q  [MROWS*DIM];
__device__ __half g_k  [MROWS*DIM];
__device__ __half g_v  [MROWS*DIM];
__device__ __half g_ctx[MROWS*DIM];
__device__ __half g_h1t[MROWS*DIM];
__device__ __half g_ffn[MROWS*HID];
__device__ __half g_xt [MROWS*DIM];
__device__ __half g_wqh[DIM*DIM];
__device__ __half g_wkh[DIM*DIM];
__device__ __half g_wvh[DIM*DIM];
__device__ __half g_woh[DIM*DIM];
__device__ __half g_w1h[DIM*HID];
__device__ __half g_w2h[HID*DIM];
__device__ __half g_saH[MROWS*DIM];
__device__ __half g_f2H[MROWS*DIM];
__device__ float  g_h1 [MROWS*DIM];

__device__ __forceinline__ uint32_t smem_u32(const void* p) {
    uint32_t a;
    asm("{ .reg .u64 t; cvta.to.shared.u64 t, %1; cvt.u32.u64 %0, t; }" : "=r"(a) : "l"(p));
    return a;
}
__device__ __forceinline__ void cp_async16(uint32_t dst, const void* src) {
    asm volatile("cp.async.cg.shared.global [%0], [%1], 16;" :: "r"(dst), "l"(src));
}
#define CP_COMMIT() asm volatile("cp.async.commit_group;" ::: "memory")
#define CP_WAIT(n)  asm volatile("cp.async.wait_group %0;" :: "n"(n) : "memory")

__device__ __forceinline__ void ldmatrix_x4(uint32_t& r0, uint32_t& r1, uint32_t& r2, uint32_t& r3,
                                            uint32_t addr) {
    asm volatile("ldmatrix.sync.aligned.m8n8.x4.shared.b16 {%0,%1,%2,%3}, [%4];"
        : "=r"(r0), "=r"(r1), "=r"(r2), "=r"(r3) : "r"(addr));
}
__device__ __forceinline__ void ldmatrix_x4_trans(uint32_t& r0, uint32_t& r1, uint32_t& r2, uint32_t& r3,
                                                  uint32_t addr) {
    asm volatile("ldmatrix.sync.aligned.m8n8.x4.trans.shared.b16 {%0,%1,%2,%3}, [%4];"
        : "=r"(r0), "=r"(r1), "=r"(r2), "=r"(r3) : "r"(addr));
}

__device__ __forceinline__ void mma_f16(float* d,
                                        uint32_t a0, uint32_t a1, uint32_t a2, uint32_t a3,
                                        uint32_t b0, uint32_t b1) {
    asm volatile(
        "mma.sync.aligned.m16n8k16.row.col.f32.f16.f16.f32 "
        "{%0,%1,%2,%3}, {%4,%5,%6,%7}, {%8,%9}, {%0,%1,%2,%3};"
        : "+f"(d[0]), "+f"(d[1]), "+f"(d[2]), "+f"(d[3])
        : "r"(a0), "r"(a1), "r"(a2), "r"(a3), "r"(b0), "r"(b1));
}

__device__ __forceinline__ uint32_t pack_h2(float a, float b) {
    __half2 h = __floats2half2_rn(a, b);
    return *(uint32_t*)&h;
}

__device__ __forceinline__ float gelu_f(float x) {
    return 0.5f * x * (1.0f + erff(x * 0.70710678118654752f));
}

// ---------------- merged prep: fp32 -> fp16 for x + all 6 weights ----------------
#define C_X  (MROWS*DIM/4)
#define C_W  (DIM*DIM/4)
#define C_F  (DIM*HID/4)
#define CB1  (C_X)
#define CB2  (CB1 + C_W)
#define CB3  (CB2 + C_W)
#define CB4  (CB3 + C_W)
#define CB5  (CB4 + C_W)
#define CB6  (CB5 + C_F)
#define CB7  (CB6 + C_F)

__global__ void cvt_all_kernel(const float* __restrict__ x,
                               const float* __restrict__ wq, const float* __restrict__ wk,
                               const float* __restrict__ wv, const float* __restrict__ wo,
                               const float* __restrict__ w1, const float* __restrict__ w2,
                               __half* __restrict__ xt,
                               __half* __restrict__ wqh, __half* __restrict__ wkh,
                               __half* __restrict__ wvh, __half* __restrict__ woh,
                               __half* __restrict__ w1h, __half* __restrict__ w2h) {
    for (int i = blockIdx.x * blockDim.x + threadIdx.x; i < CB7; i += gridDim.x * blockDim.x) {
        const float* in;
        __half* out;
        int off;
        if      (i < CB1) { in = x;  out = xt;  off = i; }
        else if (i < CB2) { in = wq; out = wqh; off = i - CB1; }
        else if (i < CB3) { in = wk; out = wkh; off = i - CB2; }
        else if (i < CB4) { in = wv; out = wvh; off = i - CB3; }
        else if (i < CB5) { in = wo; out = woh; off = i - CB4; }
        else if (i < CB6) { in = w1; out = w1h; off = i - CB5; }
        else              { in = w2; out = w2h; off = i - CB6; }
        float4 v = ((const float4*)in)[off];
        uint2 u;
        u.x = pack_h2(v.x, v.y);
        u.y = pack_h2(v.z, v.w);
        ((uint2*)out)[off] = u;
    }
}

// ---------------- fp16 GEMM: 128x128 CTA, 8 warps (R13 champion config) ----------------
#define AS 72
#define BT 136
#define A_TILE_BYTES (128 * AS * 2)
#define B_TILE_BYTES (64 * BT * 2)
#define G_STAGE_BYTES (A_TILE_BYTES + B_TILE_BYTES)
#define GEMM_SMEM_BYTES (3 * G_STAGE_BYTES)

template<int ACT, int HOUT>
__device__ __forceinline__ void gemm_body(const __half* __restrict__ A,
                                          const __half* __restrict__ W,
                                          const float* __restrict__ bias,
                                          void* __restrict__ Cv,
                                          int K, int N, int m0, int n0, float oscale) {
    extern __shared__ uint32_t dsm[];
    const uint32_t sb = smem_u32(dsm);

    const int tid  = threadIdx.x;
    const int lane = tid & 31;
    const int wid  = tid >> 5;
    const int grp  = lane >> 2;
    const int t4   = lane & 3;
    const int ts   = lane >> 3;
    const int r8   = lane & 7;
    const int wm = (wid & 3) * 32;
    const int wn = (wid >> 2) * 64;

    const uint32_t a_loff = (uint32_t)((((ts & 1) * 8 + r8) * AS) * 2 + (ts >> 1) * 16);
    const uint32_t b_loff = (uint32_t)((((ts & 1) * 8 + r8) * BT) * 2 + (ts >> 1) * 16);

    float acc[2][8][4];
    #pragma unroll
    for (int i = 0; i < 2; i++)
        #pragma unroll
        for (int j = 0; j < 8; j++)
            #pragma unroll
            for (int c = 0; c < 4; c++) acc[i][j][c] = 0.0f;

    const int nit = K / 64;

    auto load_stage = [&](int s, int it) {
        const uint32_t base = sb + (uint32_t)s * G_STAGE_BYTES;
        #pragma unroll
        for (int j = 0; j < 4; j++) {
            int idx = tid + j * 256;
            int row = idx >> 3, c = idx & 7;
            cp_async16(base + (uint32_t)(row * AS * 2 + c * 16),
                       A + (size_t)(m0 + row) * K + it * 64 + c * 8);
        }
        #pragma unroll
        for (int j = 0; j < 4; j++) {
            int idx = tid + j * 256;
            int k = idx >> 4, nb = (idx & 15) * 8;
            cp_async16(base + (uint32_t)A_TILE_BYTES + (uint32_t)(k * BT * 2 + nb * 2),
                       W + (size_t)(it * 64 + k) * N + n0 + nb);
        }
    };

    load_stage(0, 0);
    CP_COMMIT();
    if (nit > 1) { load_stage(1, 1); }
    CP_COMMIT();

    for (int it = 0; it < nit; it++) {
        const int s = it % 3;
        CP_WAIT(1);
        __syncthreads();
        if (it + 2 < nit) load_stage((it + 2) % 3, it + 2);
        CP_COMMIT();

        const uint32_t sA = sb + (uint32_t)s * G_STAGE_BYTES + (uint32_t)(wm * AS * 2) + a_loff;
        const uint32_t sB = sb + (uint32_t)s * G_STAGE_BYTES + (uint32_t)A_TILE_BYTES
                          + (uint32_t)(wn * 2) + b_loff;
        #pragma unroll
        for (int kk = 0; kk < 4; kk++) {
            uint32_t afr[2][4];
            #pragma unroll
            for (int mt = 0; mt < 2; mt++)
                ldmatrix_x4(afr[mt][0], afr[mt][1], afr[mt][2], afr[mt][3],
                            sA + (uint32_t)(mt * 16 * AS * 2) + (uint32_t)(kk * 32));
            uint32_t bfr[8][2];
            #pragma unroll
            for (int np = 0; np < 4; np++)
                ldmatrix_x4_trans(bfr[2*np][0], bfr[2*np][1], bfr[2*np+1][0], bfr[2*np+1][1],
                                  sB + (uint32_t)(kk * 16 * BT * 2) + (uint32_t)(np * 32));
            #pragma unroll
            for (int mt = 0; mt < 2; mt++)
                #pragma unroll
                for (int nt = 0; nt < 8; nt++)
                    mma_f16(acc[mt][nt], afr[mt][0], afr[mt][1], afr[mt][2], afr[mt][3],
                            bfr[nt][0], bfr[nt][1]);
        }
    }

    #pragma unroll
    for (int mt = 0; mt < 2; mt++) {
        #pragma unroll
        for (int nt = 0; nt < 8; nt++) {
            const int col = n0 + wn + nt * 8 + t4 * 2;
            const float2 bv2 = *(const float2*)&bias[col];
            const int r0 = m0 + wm + mt * 16 + grp;
            float v0 = (acc[mt][nt][0] + bv2.x) * oscale;
            float v1 = (acc[mt][nt][1] + bv2.y) * oscale;
            float v2 = (acc[mt][nt][2] + bv2.x) * oscale;
            float v3 = (acc[mt][nt][3] + bv2.y) * oscale;
            if (ACT == 1) { v0 = gelu_f(v0); v1 = gelu_f(v1); v2 = gelu_f(v2); v3 = gelu_f(v3); }
            if (HOUT) {
                __half* Ch = (__half*)Cv;
                *(uint32_t*)&Ch[(size_t)r0 * N + col]       = pack_h2(v0, v1);
                *(uint32_t*)&Ch[(size_t)(r0 + 8) * N + col] = pack_h2(v2, v3);
            } else {
                float* Cf = (float*)Cv;
                *(float2*)&Cf[(size_t)r0 * N + col]       = make_float2(v0, v1);
                *(float2*)&Cf[(size_t)(r0 + 8) * N + col] = make_float2(v2, v3);
            }
        }
    }
}

template<int ACT, int HOUT>
__global__ void __launch_bounds__(256, 2)
gemm_cp(const __half* __restrict__ A, const __half* __restrict__ W,
        const float* __restrict__ bias, void* __restrict__ C, int K, int N) {
    gemm_body<ACT, HOUT>(A, W, bias, C, K, N, blockIdx.y * 128, blockIdx.x * 128, 1.0f);
}

__global__ void __launch_bounds__(256, 2)
qkv_gemm(const __half* __restrict__ xt,
         const __half* __restrict__ wq, const __half* __restrict__ wk, const __half* __restrict__ wv,
         const float* __restrict__ bq, const float* __restrict__ bk, const float* __restrict__ bv,
         __half* __restrict__ q, __half* __restrict__ k, __half* __restrict__ v) {
    const int sel = blockIdx.x >> 3;
    const __half* W   = (sel == 0) ? wq : (sel == 1) ? wk : wv;
    const float* bias = (sel == 0) ? bq : (sel == 1) ? bk : bv;
    __half*      C    = (sel == 0) ? q  : (sel == 1) ? k  : v;
    const float scale = (sel == 0) ? 0.125f : 1.0f;
    gemm_body<0, 1>(xt, W, bias, C, DIM, DIM, blockIdx.y * 128, (blockIdx.x & 7) * 128, scale);
}

// ---------------- fp16 flash attention: 3-stage K/V pipeline (R13) ----------------
#define HS 72
#define AT_QB  (128 * HS * 2)
#define AT_TB  (64 * HS * 2)
#define AT_STAGE (2 * AT_TB)
#define ATTN_SMEM_BYTES (AT_QB + 3 * AT_STAGE + 768)

__global__ void __launch_bounds__(256, 2)
attn_mma(const __half* __restrict__ Q, const __half* __restrict__ K,
         const __half* __restrict__ V, const int* __restrict__ mask,
         __half* __restrict__ ctx) {
    extern __shared__ uint32_t asm_[];
    const uint32_t sb = smem_u32(asm_);
    float* smaskb = (float*)((char*)asm_ + AT_QB + 3 * AT_STAGE);

    const int tid  = threadIdx.x;
    const int lane = tid & 31;
    const int wid  = tid >> 5;
    const int grp  = lane >> 2;
    const int t4   = lane & 3;
    const int ts   = lane >> 3;
    const int r8   = lane & 7;
    const int w16  = wid * 16;
    const int q0 = blockIdx.x * 128;
    const int h  = blockIdx.y;
    const int b  = blockIdx.z;
    const size_t base = (size_t)b * SEQ * DIM + h * DPH;

    const uint32_t q_loff = (uint32_t)(((w16 + (ts & 1) * 8 + r8) * HS) * 2 + (ts >> 1) * 16);
    const uint32_t k_loff = (uint32_t)((((ts >> 1) * 8 + r8) * HS) * 2 + (ts & 1) * 16);
    const uint32_t v_loff = (uint32_t)((((ts & 1) * 8 + r8) * HS) * 2 + (ts >> 1) * 16);

    float o[8][4];
    #pragma unroll
    for (int nf = 0; nf < 8; nf++)
        #pragma unroll
        for (int c = 0; c < 4; c++) o[nf][c] = 0.0f;
    float mrow0 = -INFINITY, mrow1 = -INFINITY;
    float l0 = 0.0f, l1 = 0.0f;

    auto load_kv = [&](int s, int it) {
        const uint32_t kb = sb + (uint32_t)AT_QB + (uint32_t)s * AT_STAGE;
        const int kv0 = it * 64;
        #pragma unroll
        for (int j = 0; j < 2; j++) {
            int idx = tid + j * 256;
            int row = idx >> 3, c = idx & 7;
            size_t g = base + (size_t)(kv0 + row) * DIM + c * 8;
            cp_async16(kb + (uint32_t)(row * HS * 2 + c * 16), K + g);
            cp_async16(kb + (uint32_t)AT_TB + (uint32_t)(row * HS * 2 + c * 16), V + g);
        }
        if (tid < 64)
            smaskb[s * 64 + tid] = (mask[b * SEQ + kv0 + tid] == 0) ? -INFINITY : 0.0f;
    };

    {
        #pragma unroll
        for (int j = 0; j < 4; j++) {
            int idx = tid + j * 256;
            int row = idx >> 3, c = idx & 7;
            cp_async16(sb + (uint32_t)(row * HS * 2 + c * 16),
                       Q + base + (size_t)(q0 + row) * DIM + c * 8);
        }
        load_kv(0, 0);
        CP_COMMIT();
        load_kv(1, 1);
        CP_COMMIT();
    }

    const int nt_tiles = SEQ / 64;
    for (int it = 0; it < nt_tiles; it++) {
        const int s = it % 3;
        CP_WAIT(1);
        __syncthreads();
        if (it + 2 < nt_tiles) load_kv((it + 2) % 3, it + 2);
        CP_COMMIT();

        const uint32_t sbK = sb + (uint32_t)AT_QB + (uint32_t)s * AT_STAGE + k_loff;
        const uint32_t sbV = sb + (uint32_t)AT_QB + (uint32_t)s * AT_STAGE + (uint32_t)AT_TB + v_loff;
        const float* smask = smaskb + s * 64;

        float sacc[8][4];
        #pragma unroll
        for (int nf = 0; nf < 8; nf++)
            #pragma unroll
            for (int c = 0; c < 4; c++) sacc[nf][c] = 0.0f;
        #pragma unroll
        for (int kk = 0; kk < 4; kk++) {
            const uint32_t kb = kk * 32;
            uint32_t qa0, qa1, qa2, qa3;
            ldmatrix_x4(qa0, qa1, qa2, qa3, sb + q_loff + kb);
            #pragma unroll
            for (int np = 0; np < 4; np++) {
                uint32_t b00, b01, b10, b11;
                ldmatrix_x4(b00, b01, b10, b11,
                            sbK + (uint32_t)(np * 16 * HS * 2) + kb);
                mma_f16(sacc[2*np],   qa0, qa1, qa2, qa3, b00, b01);
                mma_f16(sacc[2*np+1], qa0, qa1, qa2, qa3, b10, b11);
            }
        }

        #pragma unroll
        for (int nf = 0; nf < 8; nf++) {
            float mv0 = smask[nf * 8 + t4 * 2];
            float mv1 = smask[nf * 8 + t4 * 2 + 1];
            sacc[nf][0] += mv0; sacc[nf][1] += mv1;
            sacc[nf][2] += mv0; sacc[nf][3] += mv1;
        }

        float mt0 = -INFINITY, mt1 = -INFINITY;
        #pragma unroll
        for (int nf = 0; nf < 8; nf++) {
            mt0 = fmaxf(mt0, fmaxf(sacc[nf][0], sacc[nf][1]));
            mt1 = fmaxf(mt1, fmaxf(sacc[nf][2], sacc[nf][3]));
        }
        mt0 = fmaxf(mt0, __shfl_xor_sync(0xffffffffu, mt0, 1));
        mt0 = fmaxf(mt0, __shfl_xor_sync(0xffffffffu, mt0, 2));
        mt1 = fmaxf(mt1, __shfl_xor_sync(0xffffffffu, mt1, 1));
        mt1 = fmaxf(mt1, __shfl_xor_sync(0xffffffffu, mt1, 2));
        float mnew0 = fmaxf(mrow0, mt0);
        float mnew1 = fmaxf(mrow1, mt1);
        float alpha0 = __expf(mrow0 - mnew0);
        float alpha1 = __expf(mrow1 - mnew1);
        float lsum0 = 0.0f, lsum1 = 0.0f;
        #pragma unroll
        for (int nf = 0; nf < 8; nf++) {
            sacc[nf][0] = __expf(sacc[nf][0] - mnew0);
            sacc[nf][1] = __expf(sacc[nf][1] - mnew0);
            sacc[nf][2] = __expf(sacc[nf][2] - mnew1);
            sacc[nf][3] = __expf(sacc[nf][3] - mnew1);
            lsum0 += sacc[nf][0] + sacc[nf][1];
            lsum1 += sacc[nf][2] + sacc[nf][3];
        }
        lsum0 += __shfl_xor_sync(0xffffffffu, lsum0, 1);
        lsum0 += __shfl_xor_sync(0xffffffffu, lsum0, 2);
        lsum1 += __shfl_xor_sync(0xffffffffu, lsum1, 1);
        lsum1 += __shfl_xor_sync(0xffffffffu, lsum1, 2);
        l0 = l0 * alpha0 + lsum0;
        l1 = l1 * alpha1 + lsum1;
        mrow0 = mnew0; mrow1 = mnew1;
        #pragma unroll
        for (int nf = 0; nf < 8; nf++) {
            o[nf][0] *= alpha0; o[nf][1] *= alpha0;
            o[nf][2] *= alpha1; o[nf][3] *= alpha1;
        }

        #pragma unroll
        for (int c = 0; c < 4; c++) {
            uint32_t a0 = pack_h2(sacc[2*c][0],   sacc[2*c][1]);
            uint32_t a1 = pack_h2(sacc[2*c][2],   sacc[2*c][3]);
            uint32_t a2 = pack_h2(sacc[2*c+1][0], sacc[2*c+1][1]);
            uint32_t a3 = pack_h2(sacc[2*c+1][2], sacc[2*c+1][3]);
            const uint32_t rowoff = (uint32_t)(c * 16 * HS * 2);
            #pragma unroll
            for (int np = 0; np < 4; np++) {
                uint32_t b00, b01, b10, b11;
                ldmatrix_x4_trans(b00, b01, b10, b11,
                                  sbV + rowoff + (uint32_t)(np * 32));
                mma_f16(o[2*np],   a0, a1, a2, a3, b00, b01);
                mma_f16(o[2*np+1], a0, a1, a2, a3, b10, b11);
            }
        }
    }

    const float inv0 = 1.0f / l0;
    const float inv1 = 1.0f / l1;
    const int r0 = q0 + w16 + grp;
    #pragma unroll
    for (int nf = 0; nf < 8; nf++) {
        const int d0 = nf * 8 + t4 * 2;
        *(uint32_t*)&ctx[base + (size_t)r0 * DIM + d0] =
            pack_h2(o[nf][0] * inv0, o[nf][1] * inv0);
        *(uint32_t*)&ctx[base + (size_t)(r0 + 8) * DIM + d0] =
            pack_h2(o[nf][2] * inv1, o[nf][3] * inv1);
    }
}

// ---------------- residual + LayerNorm: a fp16, residual fp32 (R13 form) ----------------
template<int HOUT>
__global__ void ln_residual_kernel(const __half* __restrict__ a,
                                   const float* __restrict__ r,
                                   const float* __restrict__ gamma,
                                   const float* __restrict__ beta,
                                   float* __restrict__ out,
                                   __half* __restrict__ out_t) {
    const int row = blockIdx.x;
    const int tid = threadIdx.x;

    uint2 ua = ((const uint2*)(a + (size_t)row * DIM))[tid];
    __half2 a01 = *(__half2*)&ua.x;
    __half2 a23 = *(__half2*)&ua.y;
    float4 vr = ((const float4*)(r + (size_t)row * DIM))[tid];
    float v[4] = { __low2float(a01) + vr.x, __high2float(a01) + vr.y,
                   __low2float(a23) + vr.z, __high2float(a23) + vr.w };
    float sum = v[0] + v[1] + v[2] + v[3];
    float sq  = v[0]*v[0] + v[1]*v[1] + v[2]*v[2] + v[3]*v[3];

    #pragma unroll
    for (int off = 16; off >= 1; off >>= 1) {
        sum += __shfl_xor_sync(0xffffffffu, sum, off);
        sq  += __shfl_xor_sync(0xffffffffu, sq,  off);
    }
    __shared__ float ssum[8], ssq[8];
    int warp = tid >> 5, lane = tid & 31;
    if (lane == 0) { ssum[warp] = sum; ssq[warp] = sq; }
    __syncthreads();
    sum = 0.0f; sq = 0.0f;
    #pragma unroll
    for (int i = 0; i < 8; i++) { sum += ssum[i]; sq += ssq[i]; }

    const float invN = 1.0f / (float)DIM;
    float mu  = sum * invN;
    float var = fmaxf(sq * invN - mu * mu, 0.0f);
    float rstd = rsqrtf(var + 1e-12f);

    float4 g4 = ((const float4*)gamma)[tid];
    float4 b4 = ((const float4*)beta)[tid];
    float4 o4;
    o4.x = (v[0] - mu) * rstd * g4.x + b4.x;
    o4.y = (v[1] - mu) * rstd * g4.y + b4.y;
    o4.z = (v[2] - mu) * rstd * g4.z + b4.z;
    o4.w = (v[3] - mu) * rstd * g4.w + b4.w;
    ((float4*)(out + (size_t)row * DIM))[tid] = o4;
    if (HOUT) {
        uint2 u;
        u.x = pack_h2(o4.x, o4.y);
        u.y = pack_h2(o4.z, o4.w);
        ((uint2*)(out_t + (size_t)row * DIM))[tid] = u;
    }
}

// ---------------- launch ----------------
extern "C" void kernel_launch(void* const* d_in, const int* in_sizes, int n_in,
                              void* d_out, int out_size) {
    const float* x    = (const float*)d_in[0];
    const int*   mask = (const int*)  d_in[1];
    const float* Wq   = (const float*)d_in[2];
    const float* bq   = (const float*)d_in[3];
    const float* Wk   = (const float*)d_in[4];
    const float* bk   = (const float*)d_in[5];
    const float* Wv   = (const float*)d_in[6];
    const float* bv   = (const float*)d_in[7];
    const float* Wo   = (const float*)d_in[8];
    const float* bo   = (const float*)d_in[9];
    const float* ln1g = (const float*)d_in[10];
    const float* ln1b = (const float*)d_in[11];
    const float* W1   = (const float*)d_in[12];
    const float* b1   = (const float*)d_in[13];
    const float* W2   = (const float*)d_in[14];
    const float* b2   = (const float*)d_in[15];
    const float* ln2g = (const float*)d_in[16];
    const float* ln2b = (const float*)d_in[17];
    float* out = (float*)d_out;

    __half *q, *k, *v, *ctx, *h1t, *ffn, *xt, *wqh, *wkh, *wvh, *woh, *w1h, *w2h, *saH, *f2H;
    float *h1;
    cudaGetSymbolAddress((void**)&q,   g_q);
    cudaGetSymbolAddress((void**)&k,   g_k);
    cudaGetSymbolAddress((void**)&v,   g_v);
    cudaGetSymbolAddress((void**)&ctx, g_ctx);
    cudaGetSymbolAddress((void**)&h1t, g_h1t);
    cudaGetSymbolAddress((void**)&ffn, g_ffn);
    cudaGetSymbolAddress((void**)&xt,  g_xt);
    cudaGetSymbolAddress((void**)&wqh, g_wqh);
    cudaGetSymbolAddress((void**)&wkh, g_wkh);
    cudaGetSymbolAddress((void**)&wvh, g_wvh);
    cudaGetSymbolAddress((void**)&woh, g_woh);
    cudaGetSymbolAddress((void**)&w1h, g_w1h);
    cudaGetSymbolAddress((void**)&w2h, g_w2h);
    cudaGetSymbolAddress((void**)&saH, g_saH);
    cudaGetSymbolAddress((void**)&f2H, g_f2H);
    cudaGetSymbolAddress((void**)&h1,  g_h1);

    cudaFuncSetAttribute(qkv_gemm,      cudaFuncAttributeMaxDynamicSharedMemorySize, GEMM_SMEM_BYTES);
    cudaFuncSetAttribute(gemm_cp<0,1>,  cudaFuncAttributeMaxDynamicSharedMemorySize, GEMM_SMEM_BYTES);
    cudaFuncSetAttribute(gemm_cp<1,1>,  cudaFuncAttributeMaxDynamicSharedMemorySize, GEMM_SMEM_BYTES);
    cudaFuncSetAttribute(attn_mma,      cudaFuncAttributeMaxDynamicSharedMemorySize, ATTN_SMEM_BYTES);

    // single merged prep pass
    cvt_all_kernel<<<2048, 256>>>(x, Wq, Wk, Wv, Wo, W1, W2,
                                  xt, wqh, wkh, wvh, woh, w1h, w2h);

    // fused QKV (fp16 out; q pre-scaled by 0.125)
    qkv_gemm<<<dim3(24, MROWS/128), 256, GEMM_SMEM_BYTES>>>(xt, wqh, wkh, wvh, bq, bk, bv, q, k, v);

    // attention (fp16 in/out)
    attn_mma<<<dim3(SEQ/128, NH, BS), 256, ATTN_SMEM_BYTES>>>(q, k, v, mask, ctx);

    // Wo projection -> sa fp16
    gemm_cp<0,1><<<dim3(DIM/128, MROWS/128), 256, GEMM_SMEM_BYTES>>>(ctx, woh, bo, saH, DIM, DIM);

    // LN1(sa + x) -> h1 fp32 + h1t fp16
    ln_residual_kernel<1><<<MROWS, 256>>>(saH, x, ln1g, ln1b, h1, h1t);

    // FFN1 (gelu, fp16 out), FFN2 (fp16 out)
    gemm_cp<1,1><<<dim3(HID/128, MROWS/128), 256, GEMM_SMEM_BYTES>>>(h1t, w1h, b1, ffn, DIM, HID);
    gemm_cp<0,1><<<dim3(DIM/128, MROWS/128), 256, GEMM_SMEM_BYTES>>>(ffn, w2h, b2, f2H, HID, DIM);

    // LN2(f2 + h1) -> out
    ln_residual_kernel<0><<<MROWS, 256>>>(f2H, h1, ln2g, ln2b, out, nullptr);
}

// round 17
// speedup vs baseline: 1.0683x; 1.0229x over previous
#include <cuda_runtime.h>
#include <cuda_fp16.h>
#include <math.h>
#include <stdint.h>

#define BS   2
#define SEQ  2048
#define DIM  1024
#define HID  4096
#define NH   16
#define DPH  64
#define MROWS (BS*SEQ)   // 4096

// ---------------- scratch (no allocation allowed) ----------------
__device__ __half g_q  [MROWS*DIM];
__device__ __half g_k  [MROWS*DIM];
__device__ __half g_v  [MROWS*DIM];
__device__ __half g_ctx[MROWS*DIM];
__device__ __half g_h1t[MROWS*DIM];
__device__ __half g_ffn[MROWS*HID];
__device__ __half g_xt [MROWS*DIM];
__device__ __half g_wqh[DIM*DIM];
__device__ __half g_wkh[DIM*DIM];
__device__ __half g_wvh[DIM*DIM];
__device__ __half g_woh[DIM*DIM];
__device__ __half g_w1h[DIM*HID];
__device__ __half g_w2h[HID*DIM];
__device__ __half g_saH[MROWS*DIM];
__device__ __half g_f2H[MROWS*DIM];
__device__ float  g_h1 [MROWS*DIM];

__device__ __forceinline__ uint32_t smem_u32(const void* p) {
    uint32_t a;
    asm("{ .reg .u64 t; cvta.to.shared.u64 t, %1; cvt.u32.u64 %0, t; }" : "=r"(a) : "l"(p));
    return a;
}
__device__ __forceinline__ void cp_async16(uint32_t dst, const void* src) {
    asm volatile("cp.async.cg.shared.global [%0], [%1], 16;" :: "r"(dst), "l"(src));
}
#define CP_COMMIT() asm volatile("cp.async.commit_group;" ::: "memory")
#define CP_WAIT(n)  asm volatile("cp.async.wait_group %0;" :: "n"(n) : "memory")

__device__ __forceinline__ void ldmatrix_x4(uint32_t& r0, uint32_t& r1, uint32_t& r2, uint32_t& r3,
                                            uint32_t addr) {
    asm volatile("ldmatrix.sync.aligned.m8n8.x4.shared.b16 {%0,%1,%2,%3}, [%4];"
        : "=r"(r0), "=r"(r1), "=r"(r2), "=r"(r3) : "r"(addr));
}
__device__ __forceinline__ void ldmatrix_x4_trans(uint32_t& r0, uint32_t& r1, uint32_t& r2, uint32_t& r3,
                                                  uint32_t addr) {
    asm volatile("ldmatrix.sync.aligned.m8n8.x4.trans.shared.b16 {%0,%1,%2,%3}, [%4];"
        : "=r"(r0), "=r"(r1), "=r"(r2), "=r"(r3) : "r"(addr));
}

__device__ __forceinline__ void mma_f16(float* d,
                                        uint32_t a0, uint32_t a1, uint32_t a2, uint32_t a3,
                                        uint32_t b0, uint32_t b1) {
    asm volatile(
        "mma.sync.aligned.m16n8k16.row.col.f32.f16.f16.f32 "
        "{%0,%1,%2,%3}, {%4,%5,%6,%7}, {%8,%9}, {%0,%1,%2,%3};"
        : "+f"(d[0]), "+f"(d[1]), "+f"(d[2]), "+f"(d[3])
        : "r"(a0), "r"(a1), "r"(a2), "r"(a3), "r"(b0), "r"(b1));
}

__device__ __forceinline__ uint32_t pack_h2(float a, float b) {
    __half2 h = __floats2half2_rn(a, b);
    return *(uint32_t*)&h;
}

// bare EX2 (scores are pre-scaled by log2e via the q epilogue scale)
__device__ __forceinline__ float ex2f(float x) {
    float r;
    asm("ex2.approx.ftz.f32 %0, %1;" : "=f"(r) : "f"(x));
    return r;
}

__device__ __forceinline__ float gelu_f(float x) {
    return 0.5f * x * (1.0f + erff(x * 0.70710678118654752f));
}

// ---------------- merged prep: fp32 -> fp16 for x + all 6 weights ----------------
#define C_X  (MROWS*DIM/4)
#define C_W  (DIM*DIM/4)
#define C_F  (DIM*HID/4)
#define CB1  (C_X)
#define CB2  (CB1 + C_W)
#define CB3  (CB2 + C_W)
#define CB4  (CB3 + C_W)
#define CB5  (CB4 + C_W)
#define CB6  (CB5 + C_F)
#define CB7  (CB6 + C_F)

__global__ void cvt_all_kernel(const float* __restrict__ x,
                               const float* __restrict__ wq, const float* __restrict__ wk,
                               const float* __restrict__ wv, const float* __restrict__ wo,
                               const float* __restrict__ w1, const float* __restrict__ w2,
                               __half* __restrict__ xt,
                               __half* __restrict__ wqh, __half* __restrict__ wkh,
                               __half* __restrict__ wvh, __half* __restrict__ woh,
                               __half* __restrict__ w1h, __half* __restrict__ w2h) {
    for (int i = blockIdx.x * blockDim.x + threadIdx.x; i < CB7; i += gridDim.x * blockDim.x) {
        const float* in;
        __half* out;
        int off;
        if      (i < CB1) { in = x;  out = xt;  off = i; }
        else if (i < CB2) { in = wq; out = wqh; off = i - CB1; }
        else if (i < CB3) { in = wk; out = wkh; off = i - CB2; }
        else if (i < CB4) { in = wv; out = wvh; off = i - CB3; }
        else if (i < CB5) { in = wo; out = woh; off = i - CB4; }
        else if (i < CB6) { in = w1; out = w1h; off = i - CB5; }
        else              { in = w2; out = w2h; off = i - CB6; }
        float4 v = ((const float4*)in)[off];
        uint2 u;
        u.x = pack_h2(v.x, v.y);
        u.y = pack_h2(v.z, v.w);
        ((uint2*)out)[off] = u;
    }
}

// ---------------- fp16 GEMM: 128x128 CTA, 8 warps (champion config) ----------------
#define AS 72
#define BT 136
#define A_TILE_BYTES (128 * AS * 2)
#define B_TILE_BYTES (64 * BT * 2)
#define G_STAGE_BYTES (A_TILE_BYTES + B_TILE_BYTES)
#define GEMM_SMEM_BYTES (3 * G_STAGE_BYTES)

template<int ACT, int HOUT>
__device__ __forceinline__ void gemm_body(const __half* __restrict__ A,
                                          const __half* __restrict__ W,
                                          const float* __restrict__ bias,
                                          void* __restrict__ Cv,
                                          int K, int N, int m0, int n0, float oscale) {
    extern __shared__ uint32_t dsm[];
    const uint32_t sb = smem_u32(dsm);

    const int tid  = threadIdx.x;
    const int lane = tid & 31;
    const int wid  = tid >> 5;
    const int grp  = lane >> 2;
    const int t4   = lane & 3;
    const int ts   = lane >> 3;
    const int r8   = lane & 7;
    const int wm = (wid & 3) * 32;
    const int wn = (wid >> 2) * 64;

    const uint32_t a_loff = (uint32_t)((((ts & 1) * 8 + r8) * AS) * 2 + (ts >> 1) * 16);
    const uint32_t b_loff = (uint32_t)((((ts & 1) * 8 + r8) * BT) * 2 + (ts >> 1) * 16);

    float acc[2][8][4];
    #pragma unroll
    for (int i = 0; i < 2; i++)
        #pragma unroll
        for (int j = 0; j < 8; j++)
            #pragma unroll
            for (int c = 0; c < 4; c++) acc[i][j][c] = 0.0f;

    const int nit = K / 64;

    auto load_stage = [&](int s, int it) {
        const uint32_t base = sb + (uint32_t)s * G_STAGE_BYTES;
        #pragma unroll
        for (int j = 0; j < 4; j++) {
            int idx = tid + j * 256;
            int row = idx >> 3, c = idx & 7;
            cp_async16(base + (uint32_t)(row * AS * 2 + c * 16),
                       A + (size_t)(m0 + row) * K + it * 64 + c * 8);
        }
        #pragma unroll
        for (int j = 0; j < 4; j++) {
            int idx = tid + j * 256;
            int k = idx >> 4, nb = (idx & 15) * 8;
            cp_async16(base + (uint32_t)A_TILE_BYTES + (uint32_t)(k * BT * 2 + nb * 2),
                       W + (size_t)(it * 64 + k) * N + n0 + nb);
        }
    };

    load_stage(0, 0);
    CP_COMMIT();
    if (nit > 1) { load_stage(1, 1); }
    CP_COMMIT();

    for (int it = 0; it < nit; it++) {
        const int s = it % 3;
        CP_WAIT(1);
        __syncthreads();
        if (it + 2 < nit) load_stage((it + 2) % 3, it + 2);
        CP_COMMIT();

        const uint32_t sA = sb + (uint32_t)s * G_STAGE_BYTES + (uint32_t)(wm * AS * 2) + a_loff;
        const uint32_t sB = sb + (uint32_t)s * G_STAGE_BYTES + (uint32_t)A_TILE_BYTES
                          + (uint32_t)(wn * 2) + b_loff;
        #pragma unroll
        for (int kk = 0; kk < 4; kk++) {
            uint32_t afr[2][4];
            #pragma unroll
            for (int mt = 0; mt < 2; mt++)
                ldmatrix_x4(afr[mt][0], afr[mt][1], afr[mt][2], afr[mt][3],
                            sA + (uint32_t)(mt * 16 * AS * 2) + (uint32_t)(kk * 32));
            uint32_t bfr[8][2];
            #pragma unroll
            for (int np = 0; np < 4; np++)
                ldmatrix_x4_trans(bfr[2*np][0], bfr[2*np][1], bfr[2*np+1][0], bfr[2*np+1][1],
                                  sB + (uint32_t)(kk * 16 * BT * 2) + (uint32_t)(np * 32));
            #pragma unroll
            for (int mt = 0; mt < 2; mt++)
                #pragma unroll
                for (int nt = 0; nt < 8; nt++)
                    mma_f16(acc[mt][nt], afr[mt][0], afr[mt][1], afr[mt][2], afr[mt][3],
                            bfr[nt][0], bfr[nt][1]);
        }
    }

    #pragma unroll
    for (int mt = 0; mt < 2; mt++) {
        #pragma unroll
        for (int nt = 0; nt < 8; nt++) {
            const int col = n0 + wn + nt * 8 + t4 * 2;
            const float2 bv2 = *(const float2*)&bias[col];
            const int r0 = m0 + wm + mt * 16 + grp;
            float v0 = (acc[mt][nt][0] + bv2.x) * oscale;
            float v1 = (acc[mt][nt][1] + bv2.y) * oscale;
            float v2 = (acc[mt][nt][2] + bv2.x) * oscale;
            float v3 = (acc[mt][nt][3] + bv2.y) * oscale;
            if (ACT == 1) { v0 = gelu_f(v0); v1 = gelu_f(v1); v2 = gelu_f(v2); v3 = gelu_f(v3); }
            if (HOUT) {
                __half* Ch = (__half*)Cv;
                *(uint32_t*)&Ch[(size_t)r0 * N + col]       = pack_h2(v0, v1);
                *(uint32_t*)&Ch[(size_t)(r0 + 8) * N + col] = pack_h2(v2, v3);
            } else {
                float* Cf = (float*)Cv;
                *(float2*)&Cf[(size_t)r0 * N + col]       = make_float2(v0, v1);
                *(float2*)&Cf[(size_t)(r0 + 8) * N + col] = make_float2(v2, v3);
            }
        }
    }
}

template<int ACT, int HOUT>
__global__ void __launch_bounds__(256, 2)
gemm_cp(const __half* __restrict__ A, const __half* __restrict__ W,
        const float* __restrict__ bias, void* __restrict__ C, int K, int N) {
    gemm_body<ACT, HOUT>(A, W, bias, C, K, N, blockIdx.y * 128, blockIdx.x * 128, 1.0f);
}

// q pre-scaled by 0.125*log2e so attention softmax uses bare ex2
#define Q_SCALE 0.180336886f   // 0.125 * 1.4426950408889634

__global__ void __launch_bounds__(256, 2)
qkv_gemm(const __half* __restrict__ xt,
         const __half* __restrict__ wq, const __half* __restrict__ wk, const __half* __restrict__ wv,
         const float* __restrict__ bq, const float* __restrict__ bk, const float* __restrict__ bv,
         __half* __restrict__ q, __half* __restrict__ k, __half* __restrict__ v) {
    const int sel = blockIdx.x >> 3;
    const __half* W   = (sel == 0) ? wq : (sel == 1) ? wk : wv;
    const float* bias = (sel == 0) ? bq : (sel == 1) ? bk : bv;
    __half*      C    = (sel == 0) ? q  : (sel == 1) ? k  : v;
    const float scale = (sel == 0) ? Q_SCALE : 1.0f;
    gemm_body<0, 1>(xt, W, bias, C, DIM, DIM, blockIdx.y * 128, (blockIdx.x & 7) * 128, scale);
}

// ---------------- fp16 flash attention: 3-stage K/V pipeline, log2-domain softmax ----------------
#define HS 72
#define AT_QB  (128 * HS * 2)
#define AT_TB  (64 * HS * 2)
#define AT_STAGE (2 * AT_TB)
#define ATTN_SMEM_BYTES (AT_QB + 3 * AT_STAGE + 768)

__global__ void __launch_bounds__(256, 2)
attn_mma(const __half* __restrict__ Q, const __half* __restrict__ K,
         const __half* __restrict__ V, const int* __restrict__ mask,
         __half* __restrict__ ctx) {
    extern __shared__ uint32_t asm_[];
    const uint32_t sb = smem_u32(asm_);
    float* smaskb = (float*)((char*)asm_ + AT_QB + 3 * AT_STAGE);

    const int tid  = threadIdx.x;
    const int lane = tid & 31;
    const int wid  = tid >> 5;
    const int grp  = lane >> 2;
    const int t4   = lane & 3;
    const int ts   = lane >> 3;
    const int r8   = lane & 7;
    const int w16  = wid * 16;
    const int q0 = blockIdx.x * 128;
    const int h  = blockIdx.y;
    const int b  = blockIdx.z;
    const size_t base = (size_t)b * SEQ * DIM + h * DPH;

    const uint32_t q_loff = (uint32_t)(((w16 + (ts & 1) * 8 + r8) * HS) * 2 + (ts >> 1) * 16);
    const uint32_t k_loff = (uint32_t)((((ts >> 1) * 8 + r8) * HS) * 2 + (ts & 1) * 16);
    const uint32_t v_loff = (uint32_t)((((ts & 1) * 8 + r8) * HS) * 2 + (ts >> 1) * 16);

    float o[8][4];
    #pragma unroll
    for (int nf = 0; nf < 8; nf++)
        #pragma unroll
        for (int c = 0; c < 4; c++) o[nf][c] = 0.0f;
    float mrow0 = -INFINITY, mrow1 = -INFINITY;
    float l0 = 0.0f, l1 = 0.0f;

    auto load_kv = [&](int s, int it) {
        const uint32_t kb = sb + (uint32_t)AT_QB + (uint32_t)s * AT_STAGE;
        const int kv0 = it * 64;
        #pragma unroll
        for (int j = 0; j < 2; j++) {
            int idx = tid + j * 256;
            int row = idx >> 3, c = idx & 7;
            size_t g = base + (size_t)(kv0 + row) * DIM + c * 8;
            cp_async16(kb + (uint32_t)(row * HS * 2 + c * 16), K + g);
            cp_async16(kb + (uint32_t)AT_TB + (uint32_t)(row * HS * 2 + c * 16), V + g);
        }
        if (tid < 64)
            smaskb[s * 64 + tid] = (mask[b * SEQ + kv0 + tid] == 0) ? -INFINITY : 0.0f;
    };

    {
        #pragma unroll
        for (int j = 0; j < 4; j++) {
            int idx = tid + j * 256;
            int row = idx >> 3, c = idx & 7;
            cp_async16(sb + (uint32_t)(row * HS * 2 + c * 16),
                       Q + base + (size_t)(q0 + row) * DIM + c * 8);
        }
        load_kv(0, 0);
        CP_COMMIT();
        load_kv(1, 1);
        CP_COMMIT();
    }

    const int nt_tiles = SEQ / 64;
    for (int it = 0; it < nt_tiles; it++) {
        const int s = it % 3;
        CP_WAIT(1);
        __syncthreads();
        if (it + 2 < nt_tiles) load_kv((it + 2) % 3, it + 2);
        CP_COMMIT();

        const uint32_t sbK = sb + (uint32_t)AT_QB + (uint32_t)s * AT_STAGE + k_loff;
        const uint32_t sbV = sb + (uint32_t)AT_QB + (uint32_t)s * AT_STAGE + (uint32_t)AT_TB + v_loff;
        const float* smask = smaskb + s * 64;

        // S' = (Q·log2e/8) K^T  — already in log2 domain
        float sacc[8][4];
        #pragma unroll
        for (int nf = 0; nf < 8; nf++)
            #pragma unroll
            for (int c = 0; c < 4; c++) sacc[nf][c] = 0.0f;
        #pragma unroll
        for (int kk = 0; kk < 4; kk++) {
            const uint32_t kb = kk * 32;
            uint32_t qa0, qa1, qa2, qa3;
            ldmatrix_x4(qa0, qa1, qa2, qa3, sb + q_loff + kb);
            #pragma unroll
            for (int np = 0; np < 4; np++) {
                uint32_t b00, b01, b10, b11;
                ldmatrix_x4(b00, b01, b10, b11,
                            sbK + (uint32_t)(np * 16 * HS * 2) + kb);
                mma_f16(sacc[2*np],   qa0, qa1, qa2, qa3, b00, b01);
                mma_f16(sacc[2*np+1], qa0, qa1, qa2, qa3, b10, b11);
            }
        }

        #pragma unroll
        for (int nf = 0; nf < 8; nf++) {
            float mv0 = smask[nf * 8 + t4 * 2];
            float mv1 = smask[nf * 8 + t4 * 2 + 1];
            sacc[nf][0] += mv0; sacc[nf][1] += mv1;
            sacc[nf][2] += mv0; sacc[nf][3] += mv1;
        }

        float mt0 = -INFINITY, mt1 = -INFINITY;
        #pragma unroll
        for (int nf = 0; nf < 8; nf++) {
            mt0 = fmaxf(mt0, fmaxf(sacc[nf][0], sacc[nf][1]));
            mt1 = fmaxf(mt1, fmaxf(sacc[nf][2], sacc[nf][3]));
        }
        mt0 = fmaxf(mt0, __shfl_xor_sync(0xffffffffu, mt0, 1));
        mt0 = fmaxf(mt0, __shfl_xor_sync(0xffffffffu, mt0, 2));
        mt1 = fmaxf(mt1, __shfl_xor_sync(0xffffffffu, mt1, 1));
        mt1 = fmaxf(mt1, __shfl_xor_sync(0xffffffffu, mt1, 2));
        float mnew0 = fmaxf(mrow0, mt0);
        float mnew1 = fmaxf(mrow1, mt1);
        float alpha0 = ex2f(mrow0 - mnew0);
        float alpha1 = ex2f(mrow1 - mnew1);
        float lsum0 = 0.0f, lsum1 = 0.0f;
        #pragma unroll
        for (int nf = 0; nf < 8; nf++) {
            sacc[nf][0] = ex2f(sacc[nf][0] - mnew0);
            sacc[nf][1] = ex2f(sacc[nf][1] - mnew0);
            sacc[nf][2] = ex2f(sacc[nf][2] - mnew1);
            sacc[nf][3] = ex2f(sacc[nf][3] - mnew1);
            lsum0 += sacc[nf][0] + sacc[nf][1];
            lsum1 += sacc[nf][2] + sacc[nf][3];
        }
        lsum0 += __shfl_xor_sync(0xffffffffu, lsum0, 1);
        lsum0 += __shfl_xor_sync(0xffffffffu, lsum0, 2);
        lsum1 += __shfl_xor_sync(0xffffffffu, lsum1, 1);
        lsum1 += __shfl_xor_sync(0xffffffffu, lsum1, 2);
        l0 = l0 * alpha0 + lsum0;
        l1 = l1 * alpha1 + lsum1;
        mrow0 = mnew0; mrow1 = mnew1;
        #pragma unroll
        for (int nf = 0; nf < 8; nf++) {
            o[nf][0] *= alpha0; o[nf][1] *= alpha0;
            o[nf][2] *= alpha1; o[nf][3] *= alpha1;
        }

        #pragma unroll
        for (int c = 0; c < 4; c++) {
            uint32_t a0 = pack_h2(sacc[2*c][0],   sacc[2*c][1]);
            uint32_t a1 = pack_h2(sacc[2*c][2],   sacc[2*c][3]);
            uint32_t a2 = pack_h2(sacc[2*c+1][0], sacc[2*c+1][1]);
            uint32_t a3 = pack_h2(sacc[2*c+1][2], sacc[2*c+1][3]);
            const uint32_t rowoff = (uint32_t)(c * 16 * HS * 2);
            #pragma unroll
            for (int np = 0; np < 4; np++) {
                uint32_t b00, b01, b10, b11;
                ldmatrix_x4_trans(b00, b01, b10, b11,
                                  sbV + rowoff + (uint32_t)(np * 32));
                mma_f16(o[2*np],   a0, a1, a2, a3, b00, b01);
                mma_f16(o[2*np+1], a0, a1, a2, a3, b10, b11);
            }
        }
    }

    const float inv0 = 1.0f / l0;
    const float inv1 = 1.0f / l1;
    const int r0 = q0 + w16 + grp;
    #pragma unroll
    for (int nf = 0; nf < 8; nf++) {
        const int d0 = nf * 8 + t4 * 2;
        *(uint32_t*)&ctx[base + (size_t)r0 * DIM + d0] =
            pack_h2(o[nf][0] * inv0, o[nf][1] * inv0);
        *(uint32_t*)&ctx[base + (size_t)(r0 + 8) * DIM + d0] =
            pack_h2(o[nf][2] * inv1, o[nf][3] * inv1);
    }
}

// ---------------- residual + LayerNorm: a fp16, residual fp32 ----------------
template<int HOUT>
__global__ void ln_residual_kernel(const __half* __restrict__ a,
                                   const float* __restrict__ r,
                                   const float* __restrict__ gamma,
                                   const float* __restrict__ beta,
                                   float* __restrict__ out,
                                   __half* __restrict__ out_t) {
    const int row = blockIdx.x;
    const int tid = threadIdx.x;

    uint2 ua = ((const uint2*)(a + (size_t)row * DIM))[tid];
    __half2 a01 = *(__half2*)&ua.x;
    __half2 a23 = *(__half2*)&ua.y;
    float4 vr = ((const float4*)(r + (size_t)row * DIM))[tid];
    float v[4] = { __low2float(a01) + vr.x, __high2float(a01) + vr.y,
                   __low2float(a23) + vr.z, __high2float(a23) + vr.w };
    float sum = v[0] + v[1] + v[2] + v[3];
    float sq  = v[0]*v[0] + v[1]*v[1] + v[2]*v[2] + v[3]*v[3];

    #pragma unroll
    for (int off = 16; off >= 1; off >>= 1) {
        sum += __shfl_xor_sync(0xffffffffu, sum, off);
        sq  += __shfl_xor_sync(0xffffffffu, sq,  off);
    }
    __shared__ float ssum[8], ssq[8];
    int warp = tid >> 5, lane = tid & 31;
    if (lane == 0) { ssum[warp] = sum; ssq[warp] = sq; }
    __syncthreads();
    sum = 0.0f; sq = 0.0f;
    #pragma unroll
    for (int i = 0; i < 8; i++) { sum += ssum[i]; sq += ssq[i]; }

    const float invN = 1.0f / (float)DIM;
    float mu  = sum * invN;
    float var = fmaxf(sq * invN - mu * mu, 0.0f);
    float rstd = rsqrtf(var + 1e-12f);

    float4 g4 = ((const float4*)gamma)[tid];
    float4 b4 = ((const float4*)beta)[tid];
    float4 o4;
    o4.x = (v[0] - mu) * rstd * g4.x + b4.x;
    o4.y = (v[1] - mu) * rstd * g4.y + b4.y;
    o4.z = (v[2] - mu) * rstd * g4.z + b4.z;
    o4.w = (v[3] - mu) * rstd * g4.w + b4.w;
    ((float4*)(out + (size_t)row * DIM))[tid] = o4;
    if (HOUT) {
        uint2 u;
        u.x = pack_h2(o4.x, o4.y);
        u.y = pack_h2(o4.z, o4.w);
        ((uint2*)(out_t + (size_t)row * DIM))[tid] = u;
    }
}

// ---------------- launch ----------------
extern "C" void kernel_launch(void* const* d_in, const int* in_sizes, int n_in,
                              void* d_out, int out_size) {
    const float* x    = (const float*)d_in[0];
    const int*   mask = (const int*)  d_in[1];
    const float* Wq   = (const float*)d_in[2];
    const float* bq   = (const float*)d_in[3];
    const float* Wk   = (const float*)d_in[4];
    const float* bk   = (const float*)d_in[5];
    const float* Wv   = (const float*)d_in[6];
    const float* bv   = (const float*)d_in[7];
    const float* Wo   = (const float*)d_in[8];
    const float* bo   = (const float*)d_in[9];
    const float* ln1g = (const float*)d_in[10];
    const float* ln1b = (const float*)d_in[11];
    const float* W1   = (const float*)d_in[12];
    const float* b1   = (const float*)d_in[13];
    const float* W2   = (const float*)d_in[14];
    const float* b2   = (const float*)d_in[15];
    const float* ln2g = (const float*)d_in[16];
    const float* ln2b = (const float*)d_in[17];
    float* out = (float*)d_out;

    __half *q, *k, *v, *ctx, *h1t, *ffn, *xt, *wqh, *wkh, *wvh, *woh, *w1h, *w2h, *saH, *f2H;
    float *h1;
    cudaGetSymbolAddress((void**)&q,   g_q);
    cudaGetSymbolAddress((void**)&k,   g_k);
    cudaGetSymbolAddress((void**)&v,   g_v);
    cudaGetSymbolAddress((void**)&ctx, g_ctx);
    cudaGetSymbolAddress((void**)&h1t, g_h1t);
    cudaGetSymbolAddress((void**)&ffn, g_ffn);
    cudaGetSymbolAddress((void**)&xt,  g_xt);
    cudaGetSymbolAddress((void**)&wqh, g_wqh);
    cudaGetSymbolAddress((void**)&wkh, g_wkh);
    cudaGetSymbolAddress((void**)&wvh, g_wvh);
    cudaGetSymbolAddress((void**)&woh, g_woh);
    cudaGetSymbolAddress((void**)&w1h, g_w1h);
    cudaGetSymbolAddress((void**)&w2h, g_w2h);
    cudaGetSymbolAddress((void**)&saH, g_saH);
    cudaGetSymbolAddress((void**)&f2H, g_f2H);
    cudaGetSymbolAddress((void**)&h1,  g_h1);

    cudaFuncSetAttribute(qkv_gemm,      cudaFuncAttributeMaxDynamicSharedMemorySize, GEMM_SMEM_BYTES);
    cudaFuncSetAttribute(gemm_cp<0,1>,  cudaFuncAttributeMaxDynamicSharedMemorySize, GEMM_SMEM_BYTES);
    cudaFuncSetAttribute(gemm_cp<1,1>,  cudaFuncAttributeMaxDynamicSharedMemorySize, GEMM_SMEM_BYTES);
    cudaFuncSetAttribute(attn_mma,      cudaFuncAttributeMaxDynamicSharedMemorySize, ATTN_SMEM_BYTES);

    // single merged prep pass
    cvt_all_kernel<<<2048, 256>>>(x, Wq, Wk, Wv, Wo, W1, W2,
                                  xt, wqh, wkh, wvh, woh, w1h, w2h);

    // fused QKV (fp16 out; q pre-scaled by 0.125*log2e)
    qkv_gemm<<<dim3(24, MROWS/128), 256, GEMM_SMEM_BYTES>>>(xt, wqh, wkh, wvh, bq, bk, bv, q, k, v);

    // attention (fp16 in/out, log2-domain softmax)
    attn_mma<<<dim3(SEQ/128, NH, BS), 256, ATTN_SMEM_BYTES>>>(q, k, v, mask, ctx);

    // Wo projection -> sa fp16
    gemm_cp<0,1><<<dim3(DIM/128, MROWS/128), 256, GEMM_SMEM_BYTES>>>(ctx, woh, bo, saH, DIM, DIM);

    // LN1(sa + x) -> h1 fp32 + h1t fp16
    ln_residual_kernel<1><<<MROWS, 256>>>(saH, x, ln1g, ln1b, h1, h1t);

    // FFN1 (gelu, fp16 out), FFN2 (fp16 out)
    gemm_cp<1,1><<<dim3(HID/128, MROWS/128), 256, GEMM_SMEM_BYTES>>>(h1t, w1h, b1, ffn, DIM, HID);
    gemm_cp<0,1><<<dim3(DIM/128, MROWS/128), 256, GEMM_SMEM_BYTES>>>(ffn, w2h, b2, f2H, HID, DIM);

    // LN2(f2 + h1) -> out
    ln_residual_kernel<0><<<MROWS, 256>>>(f2H, h1, ln2g, ln2b, out, nullptr);
}